// round 14
// baseline (speedup 1.0000x reference)
#include <cuda_runtime.h>
#include <cuda_fp16.h>
#include <math.h>
#include <stdint.h>
#include <string.h>

// Problem constants
#define BATCH 16
#define CIN   256
#define HW    4096
#define O3    1536
#define HID   512
#define NH    8
#define HD    64
#define NMEM  4
#define NC    8
#define CHUNK 512

// Scratch (device globals — allocation-free rule)
__device__ __half g_w1[O3 * CIN];
__device__ __half g_wo1[CIN * HID];
__device__ __half g_x1[(size_t)BATCH * HW * CIN];   // transposed [b][n][c], fp16
__device__ __half g_qkv[(size_t)BATCH * O3 * HW];   // 201 MB, fp16
__device__ __half g_ek[(size_t)BATCH * NH * HD * HW]; // exp(K-rmax)*rinv, fp16
__device__ float g_rmax[BATCH * NH * HD];
__device__ float g_rinv[BATCH * NH * HD];
__device__ float g_part[(size_t)NC * BATCH * NH * HD * HD];
__device__ float g_ctx[BATCH * NH * HD * HD];
__device__ __half g_a1[(size_t)BATCH * HW * HID];   // att^T [b][pos][hid], fp16

// ---- mma.sync helpers ------------------------------------------------------
__device__ __forceinline__ uint32_t smem_u32(const void* p) {
    uint32_t a;
    asm("{ .reg .u64 t; cvta.to.shared.u64 t, %1; cvt.u32.u64 %0, t; }"
        : "=r"(a) : "l"(p));
    return a;
}
__device__ __forceinline__ void ldm4(uint32_t* r, uint32_t addr) {
    asm volatile("ldmatrix.sync.aligned.m8n8.x4.shared.b16 {%0,%1,%2,%3}, [%4];"
                 : "=r"(r[0]), "=r"(r[1]), "=r"(r[2]), "=r"(r[3]) : "r"(addr));
}
__device__ __forceinline__ void mma_f16(float* c, const uint32_t* a,
                                        uint32_t b0, uint32_t b1) {
    asm volatile(
        "mma.sync.aligned.m16n8k16.row.col.f32.f16.f16.f32 "
        "{%0,%1,%2,%3}, {%4,%5,%6,%7}, {%8,%9}, {%0,%1,%2,%3};"
        : "+f"(c[0]), "+f"(c[1]), "+f"(c[2]), "+f"(c[3])
        : "r"(a[0]), "r"(a[1]), "r"(a[2]), "r"(a[3]), "r"(b0), "r"(b1));
}
__device__ __forceinline__ void cp16(uint32_t dst, const void* src) {
    asm volatile("cp.async.cg.shared.global [%0], [%1], 16;"
                 :: "r"(dst), "l"(src));
}
#define CP_COMMIT() asm volatile("cp.async.commit_group;" ::: "memory")
#define CP_WAIT1()  asm volatile("cp.async.wait_group 1;" ::: "memory")
#define CP_WAIT0()  asm volatile("cp.async.wait_group 0;" ::: "memory")

__device__ __forceinline__ uint32_t pkh(float lo, float hi) {
    __half2 t = __floats2half2_rn(lo, hi);
    uint32_t r; memcpy(&r, &t, 4); return r;
}

// ---------------------------------------------------------------------------
// Kernel 1: fused rmsnorm-scale + transpose + fp16 convert.
// ---------------------------------------------------------------------------
__global__ __launch_bounds__(256) void xnorm_kernel(const float* __restrict__ x,
                                                    __half* __restrict__ x1) {
    int b = blockIdx.y;
    int n0 = blockIdx.x * 32;
    __shared__ float t[256][33];
    __shared__ float ps[8][33];
    __shared__ float sv[32];
    int tid = threadIdx.x;
    int tx = tid & 31, ty = tid >> 5;

    const float* xb = x + (size_t)b * CIN * HW + n0;
#pragma unroll
    for (int i = 0; i < 32; i++) {
        int c = ty + i * 8;
        t[c][tx] = xb[(size_t)c * HW + tx];
    }
    __syncthreads();
    {
        float a = 0.f;
#pragma unroll
        for (int j = 0; j < 32; j++) {
            float v = t[ty * 32 + j][tx];
            a += v * v;
        }
        ps[ty][tx] = a;
    }
    __syncthreads();
    if (tid < 32) {
        float a = 0.f;
#pragma unroll
        for (int g = 0; g < 8; g++) a += ps[g][tid];
        sv[tid] = 16.0f / fmaxf(sqrtf(a), 1e-12f);
    }
    __syncthreads();
#pragma unroll
    for (int cb = 0; cb < 4; cb++) {
#pragma unroll
        for (int i = 0; i < 4; i++) {
            int nr = ty + i * 8;
            int c0 = cb * 64 + tx * 2;
            float s = sv[nr];
            uint32_t h = pkh(t[c0][nr] * s, t[c0 + 1][nr] * s);
            *(uint32_t*)((char*)x1 +
                (((size_t)b * HW + n0 + nr) * CIN + c0) * 2) = h;
        }
    }
}

// ---------------------------------------------------------------------------
// Kernel 1b / 1b2: weight converts
// ---------------------------------------------------------------------------
__global__ __launch_bounds__(256) void wconv_kernel(const float* __restrict__ w,
                                                    const float* __restrict__ g,
                                                    __half* __restrict__ w1) {
    int i = blockIdx.x * 256 + threadIdx.x;
    if (i < O3 * CIN) w1[i] = __float2half_rn(w[i] * g[i & (CIN - 1)]);
}
__global__ __launch_bounds__(256) void woconv_kernel(const float* __restrict__ w,
                                                     __half* __restrict__ w1) {
    int i = blockIdx.x * 256 + threadIdx.x;
    if (i < CIN * HID) w1[i] = __float2half_rn(w[i]);
}

// ---------------------------------------------------------------------------
// Kernel 2: QKV GEMM, mma.sync fp16, fp16 out. CTA 256x128, K-tile 32,
// LDK=40, 512 thr / 16 warps (4m x 4n), warp tile 64x32. ~2.6x less L2
// input traffic than 128x128.
// ---------------------------------------------------------------------------
#define QLDK   40
#define QA_T   (256 * QLDK * 2)        // 20480
#define QB_T   (128 * QLDK * 2)        // 10240
#define QSTAGE (QA_T + QB_T)           // 30720
#define QSMTOT (2 * QSTAGE)            // 61440
#define Q_A    0
#define Q_B    QA_T

__global__ void __launch_bounds__(512, 1)
qkv_mma_kernel(const __half* __restrict__ w1,
               const __half* __restrict__ x1,
               __half* __restrict__ out) {
    extern __shared__ char smem[];
    uint32_t sb = smem_u32(smem);
    int tid = threadIdx.x;
    int warp = tid >> 5, lane = tid & 31;
    int b = blockIdx.z;
    int rowBase = blockIdx.y * 256;
    int colBase = blockIdx.x * 128;

    const char* srcA = (const char*)(w1 + (size_t)rowBase * CIN);
    const char* srcB = (const char*)(x1 + ((size_t)b * HW + colBase) * CIN);

    int lrow = tid >> 2, lseg = tid & 3;    // 128 rows x 4 segs per pass

    auto load_stage = [&](int st, int k0) {
        uint32_t dbase = sb + st * QSTAGE;
#pragma unroll
        for (int j = 0; j < 2; j++) {       // A: 256 rows
            int row = lrow + j * 128;
            cp16(dbase + Q_A + row * (QLDK * 2) + lseg * 16,
                 srcA + (size_t)row * (CIN * 2) + k0 * 2 + lseg * 16);
        }
        {                                   // B: 128 rows
            int row = lrow;
            cp16(dbase + Q_B + row * (QLDK * 2) + lseg * 16,
                 srcB + (size_t)row * (CIN * 2) + k0 * 2 + lseg * 16);
        }
    };

    int mwarp = (warp >> 2) * 64;
    int nwarp = (warp & 3) * 32;

    float acc[4][4][4];
#pragma unroll
    for (int mi = 0; mi < 4; mi++)
#pragma unroll
        for (int nf = 0; nf < 4; nf++)
#pragma unroll
            for (int q = 0; q < 4; q++) acc[mi][nf][q] = 0.f;

    int flrow = lane & 7, mat = lane >> 3;
    int frow = (mat & 1) * 8 + flrow;
    int fk   = (mat >> 1) * 8;

    load_stage(0, 0);
    CP_COMMIT();

    for (int kt = 0; kt < 8; kt++) {
        if (kt < 7) {
            load_stage((kt + 1) & 1, (kt + 1) * 32);
            CP_COMMIT();
            CP_WAIT1();
        } else {
            CP_WAIT0();
        }
        __syncthreads();
        uint32_t stb = sb + (kt & 1) * QSTAGE;

#pragma unroll
        for (int ks = 0; ks < 2; ks++) {
            int kk = ks * 16 + fk;
            uint32_t fa[4][4], fb[2][4];
#pragma unroll
            for (int mi = 0; mi < 4; mi++)
                ldm4(fa[mi], stb + Q_A +
                     (uint32_t)((mwarp + mi * 16 + frow) * (QLDK * 2) + kk * 2));
#pragma unroll
            for (int nb = 0; nb < 2; nb++)
                ldm4(fb[nb], stb + Q_B +
                     (uint32_t)((nwarp + nb * 16 + frow) * (QLDK * 2) + kk * 2));
#pragma unroll
            for (int mi = 0; mi < 4; mi++)
#pragma unroll
                for (int nf = 0; nf < 4; nf++) {
                    int nb = nf >> 1, hi = nf & 1;
                    mma_f16(acc[mi][nf], fa[mi], fb[nb][hi], fb[nb][hi + 2]);
                }
        }
        __syncthreads();
    }

    __half* obase = out + (size_t)b * O3 * HW;
#pragma unroll
    for (int mi = 0; mi < 4; mi++) {
        int row = rowBase + mwarp + mi * 16 + (lane >> 2);
#pragma unroll
        for (int nf = 0; nf < 4; nf++) {
            int col = colBase + nwarp + nf * 8 + (lane & 3) * 2;
            *(uint32_t*)((char*)obase + ((size_t)row * HW + col) * 2) =
                pkh(acc[mi][nf][0], acc[mi][nf][1]);
            *(uint32_t*)((char*)obase + ((size_t)(row + 8) * HW + col) * 2) =
                pkh(acc[mi][nf][2], acc[mi][nf][3]);
        }
    }
}

// ---------------------------------------------------------------------------
// Kernel 3a: k-softmax stats + write ek = exp(K-rmax)*rinv (fp16)
// ---------------------------------------------------------------------------
__global__ __launch_bounds__(256) void kstats_kernel(const __half* __restrict__ qkv,
                                                     const float* __restrict__ memkv,
                                                     float* __restrict__ rmax,
                                                     float* __restrict__ rinv,
                                                     __half* __restrict__ ek) {
    int d = blockIdx.x, h = blockIdx.y, b = blockIdx.z;
    int tid = threadIdx.x;
    const __half2* kr = (const __half2*)(qkv + ((size_t)b * O3 + HID + h * HD + d) * HW);
    const float* MK = memkv + ((size_t)h * HD + d) * NMEM;

    float v[16];
#pragma unroll
    for (int i = 0; i < 8; i++) {
        float2 p = __half22float2(kr[i * 256 + tid]);
        v[2 * i] = p.x;
        v[2 * i + 1] = p.y;
    }
    float m = v[0];
#pragma unroll
    for (int i = 1; i < 16; i++) m = fmaxf(m, v[i]);
    if (tid < NMEM) m = fmaxf(m, MK[tid]);

    __shared__ float red[8];
#pragma unroll
    for (int o = 16; o; o >>= 1) m = fmaxf(m, __shfl_xor_sync(0xFFFFFFFFu, m, o));
    if ((tid & 31) == 0) red[tid >> 5] = m;
    __syncthreads();
    if (tid == 0) {
        float t = red[0];
#pragma unroll
        for (int i = 1; i < 8; i++) t = fmaxf(t, red[i]);
        red[0] = t;
    }
    __syncthreads();
    m = red[0];
    __syncthreads();

    float ss = 0.f;
#pragma unroll
    for (int i = 0; i < 16; i++) ss += __expf(v[i] - m);
    if (tid < NMEM) ss += __expf(MK[tid] - m);
#pragma unroll
    for (int o = 16; o; o >>= 1) ss += __shfl_xor_sync(0xFFFFFFFFu, ss, o);
    if ((tid & 31) == 0) red[tid >> 5] = ss;
    __syncthreads();
    if (tid == 0) {
        float t = 0.f;
#pragma unroll
        for (int i = 0; i < 8; i++) t += red[i];
        float rv = 1.0f / t;
        int idx = (b * NH + h) * HD + d;
        rmax[idx] = m;
        rinv[idx] = rv;
        red[0] = rv;
    }
    __syncthreads();
    float rv = red[0];
    __half2* ekw = (__half2*)(ek + ((size_t)(b * NH + h) * HD + d) * HW);
#pragma unroll
    for (int i = 0; i < 8; i++)
        ekw[i * 256 + tid] = __floats2half2_rn(__expf(v[2 * i] - m) * rv,
                                               __expf(v[2 * i + 1] - m) * rv);
}

// ---------------------------------------------------------------------------
// Kernel 3b: partial context via mma.sync fp16. M=64, N=64, K=512.
// ---------------------------------------------------------------------------
#define CLDK 72
#define CT_T (64 * CLDK * 2)
#define CSTAGE (2 * CT_T)

__global__ __launch_bounds__(256) void ctxpart_kernel(const __half* __restrict__ ek,
                                                      const __half* __restrict__ qkv,
                                                      float* __restrict__ part) {
    __shared__ __align__(16) char csm[2 * CSTAGE];
    uint32_t sb = smem_u32(csm);
    int tid = threadIdx.x, warp = tid >> 5, lane = tid & 31;
    int c = blockIdx.x, h = blockIdx.y, b = blockIdx.z;

    const char* srcA = (const char*)(ek + ((size_t)(b * NH + h) * HD) * HW + c * CHUNK);
    const char* srcB = (const char*)(qkv + ((size_t)b * O3 + 2 * HID + h * HD) * HW + c * CHUNK);

    int lrow = tid >> 3, lseg = tid & 7;

    auto load_stage = [&](int st, int n0) {
        uint32_t dbase = sb + st * CSTAGE;
#pragma unroll
        for (int j = 0; j < 2; j++) {
            int row = lrow + j * 32;
            uint32_t dp = dbase + row * (CLDK * 2) + lseg * 16;
            size_t go = ((size_t)row * HW + n0) * 2 + lseg * 16;
            cp16(dp, srcA + go);
            cp16(dp + CT_T, srcB + go);
        }
    };

    int mwarp = (warp >> 2) * 32;
    int nwarp = (warp & 3) * 16;

    float acc[2][2][4];
#pragma unroll
    for (int mi = 0; mi < 2; mi++)
#pragma unroll
        for (int nf = 0; nf < 2; nf++)
#pragma unroll
            for (int q = 0; q < 4; q++) acc[mi][nf][q] = 0.f;

    int flrow = lane & 7, mat = lane >> 3;
    int frow = (mat & 1) * 8 + flrow;
    int fk   = (mat >> 1) * 8;

    load_stage(0, 0);
    CP_COMMIT();

    for (int kt = 0; kt < 8; kt++) {
        if (kt < 7) {
            load_stage((kt + 1) & 1, (kt + 1) * 64);
            CP_COMMIT();
            CP_WAIT1();
        } else {
            CP_WAIT0();
        }
        __syncthreads();
        uint32_t stb = sb + (kt & 1) * CSTAGE;

#pragma unroll
        for (int ks = 0; ks < 4; ks++) {
            int kk = ks * 16 + fk;
            uint32_t fa[2][4], fb[4];
#pragma unroll
            for (int mi = 0; mi < 2; mi++)
                ldm4(fa[mi], stb +
                     (uint32_t)((mwarp + mi * 16 + frow) * (CLDK * 2) + kk * 2));
            ldm4(fb, stb + CT_T +
                 (uint32_t)((nwarp + frow) * (CLDK * 2) + kk * 2));
#pragma unroll
            for (int mi = 0; mi < 2; mi++)
#pragma unroll
                for (int nf = 0; nf < 2; nf++)
                    mma_f16(acc[mi][nf], fa[mi], fb[nf], fb[nf + 2]);
        }
        __syncthreads();
    }

    float* pb = part + ((size_t)c * BATCH * NH + b * NH + h) * (HD * HD);
#pragma unroll
    for (int mi = 0; mi < 2; mi++) {
        int d = mwarp + mi * 16 + (lane >> 2);
#pragma unroll
        for (int nf = 0; nf < 2; nf++) {
            int e = nwarp + nf * 8 + (lane & 3) * 2;
            *(float2*)(&pb[d * HD + e]) = make_float2(acc[mi][nf][0], acc[mi][nf][1]);
            *(float2*)(&pb[(d + 8) * HD + e]) = make_float2(acc[mi][nf][2], acc[mi][nf][3]);
        }
    }
}

// ---------------------------------------------------------------------------
// Kernel 3c: reduce partials + mem-kv tail -> ctx
// ---------------------------------------------------------------------------
__global__ __launch_bounds__(256) void ctxreduce_kernel(const float* __restrict__ part,
                                                        const float* __restrict__ memkv,
                                                        const float* __restrict__ rmax,
                                                        const float* __restrict__ rinv,
                                                        float* __restrict__ ctx) {
    int h = blockIdx.x, b = blockIdx.y;
    __shared__ float mkx[64][4];
    __shared__ float mvs[64][4];
    int tid = threadIdx.x;
    {
        int d = tid >> 2, j = tid & 3;
        int idx = (b * NH + h) * HD + d;
        mkx[d][j] = __expf(memkv[((size_t)h * HD + d) * NMEM + j] - rmax[idx]) * rinv[idx];
        mvs[d][j] = memkv[(size_t)NH * HD * NMEM + ((size_t)h * HD + d) * NMEM + j];
    }
    __syncthreads();
    size_t base = (size_t)(b * NH + h) * (HD * HD);
    for (int l = tid; l < HD * HD; l += 256) {
        int d = l >> 6, e = l & 63;
        float s2 = 0.f;
#pragma unroll
        for (int cc = 0; cc < NC; cc++)
            s2 += part[(size_t)cc * BATCH * NH * HD * HD + base + l];
#pragma unroll
        for (int j = 0; j < 4; j++) s2 += mkx[d][j] * mvs[e][j];
        ctx[base + l] = s2;
    }
}

// ---------------------------------------------------------------------------
// Kernel 4: q-softmax + tensorized 64x64x64 GEMM.
// ---------------------------------------------------------------------------
__global__ __launch_bounds__(256) void attend_kernel(const __half* __restrict__ qkv,
                                                     const float* __restrict__ ctx,
                                                     __half* __restrict__ a1) {
    int pos0 = blockIdx.x * 64;
    int h = blockIdx.y, b = blockIdx.z;
    const __half* Q = qkv + ((size_t)b * O3 + h * HD) * HW;
    const float* cb = ctx + (size_t)(b * NH + h) * HD * HD;

    __shared__ __align__(16) float qs[64][68];
    __shared__ __align__(16) __half cth[64][72];
    __shared__ __align__(16) __half qth[64][72];

    int tid = threadIdx.x, warp = tid >> 5, lane = tid & 31;

    for (int l = tid; l < 64 * 32; l += 256) {
        int d = l >> 5, p2 = (l & 31) * 2;
        float2 qv = __half22float2(*(const __half2*)(Q + (size_t)d * HW + pos0 + p2));
        qs[d][p2] = qv.x;
        qs[d][p2 + 1] = qv.y;
    }
    for (int l = tid; l < HD * HD; l += 256) {
        int d = l >> 6, e = l & 63;
        cth[e][d] = __float2half_rn(cb[l]);
    }
    __syncthreads();

    if (tid < 64) {
        float m = -1e30f;
#pragma unroll
        for (int d = 0; d < HD; d++) m = fmaxf(m, qs[d][tid]);
        float ss = 0.f;
#pragma unroll
        for (int d = 0; d < HD; d++) ss += __expf(qs[d][tid] - m);
        float inv = 0.125f / ss;
#pragma unroll
        for (int d = 0; d < HD; d++)
            qth[tid][d] = __float2half_rn(__expf(qs[d][tid] - m) * inv);
    }
    __syncthreads();

    int mwarp = (warp >> 2) * 32;
    int nwarp = (warp & 3) * 16;

    float acc[2][2][4];
#pragma unroll
    for (int mi = 0; mi < 2; mi++)
#pragma unroll
        for (int nf = 0; nf < 2; nf++)
#pragma unroll
            for (int q = 0; q < 4; q++) acc[mi][nf][q] = 0.f;

    int flrow = lane & 7, mat = lane >> 3;
    int frow = (mat & 1) * 8 + flrow;
    int fk   = (mat >> 1) * 8;

    uint32_t sc = smem_u32(cth), sq = smem_u32(qth);
#pragma unroll
    for (int ks = 0; ks < 4; ks++) {
        int kk = ks * 16 + fk;
        uint32_t fa[2][4], fb[4];
#pragma unroll
        for (int mi = 0; mi < 2; mi++)
            ldm4(fa[mi], sc + (uint32_t)((mwarp + mi * 16 + frow) * 144 + kk * 2));
        ldm4(fb, sq + (uint32_t)((nwarp + frow) * 144 + kk * 2));
#pragma unroll
        for (int mi = 0; mi < 2; mi++)
#pragma unroll
            for (int nf = 0; nf < 2; nf++)
                mma_f16(acc[mi][nf], fa[mi], fb[nf], fb[nf + 2]);
    }
    __syncthreads();

#pragma unroll
    for (int mi = 0; mi < 2; mi++) {
        int e = mwarp + mi * 16 + (lane >> 2);
#pragma unroll
        for (int nf = 0; nf < 2; nf++) {
            int p = nwarp + nf * 8 + (lane & 3) * 2;
            qth[p][e]         = __float2half_rn(acc[mi][nf][0]);
            qth[p + 1][e]     = __float2half_rn(acc[mi][nf][1]);
            qth[p][e + 8]     = __float2half_rn(acc[mi][nf][2]);
            qth[p + 1][e + 8] = __float2half_rn(acc[mi][nf][3]);
        }
    }
    __syncthreads();

    {
        int pos = tid >> 2, e0 = (tid & 3) * 16;
        size_t base = ((size_t)b * HW + pos0 + pos) * HID + h * HD + e0;
        uint32_t r[8];
#pragma unroll
        for (int u = 0; u < 8; u++)
            r[u] = *(const uint32_t*)(&qth[pos][e0 + 2 * u]);
        *(uint4*)((char*)a1 + base * 2)      = make_uint4(r[0], r[1], r[2], r[3]);
        *(uint4*)((char*)a1 + base * 2 + 16) = make_uint4(r[4], r[5], r[6], r[7]);
    }
}

// ---------------------------------------------------------------------------
// Kernel 5: out GEMM fp16 + bias + fused rmsnorm. CTA 256x128, K-tile 32,
// 512 thr / 16 warps (4m x 4n), warp tile 64x32.
// ---------------------------------------------------------------------------
#define OLDK   40
#define OA_T   (256 * OLDK * 2)
#define OB_T   (128 * OLDK * 2)
#define OSTAGE (OA_T + OB_T)
#define OSMTOT (2 * OSTAGE)
#define O_A    0
#define O_B    OA_T

__global__ void __launch_bounds__(512, 1)
outnorm_mma_kernel(const __half* __restrict__ wo1,
                   const __half* __restrict__ a1,
                   const float* __restrict__ bias,
                   const float* __restrict__ gout,
                   float* __restrict__ out) {
    extern __shared__ char smem[];
    uint32_t sb = smem_u32(smem);
    __shared__ float colsq[128];
    __shared__ float invs[128];

    int tid = threadIdx.x;
    int warp = tid >> 5, lane = tid & 31;
    int b = blockIdx.y;
    int pos0 = blockIdx.x * 128;

    const char* srcA = (const char*)wo1;
    const char* srcB = (const char*)(a1 + ((size_t)b * HW + pos0) * HID);

    int lrow = tid >> 2, lseg = tid & 3;

    auto load_stage = [&](int st, int k0) {
        uint32_t dbase = sb + st * OSTAGE;
#pragma unroll
        for (int j = 0; j < 2; j++) {
            int row = lrow + j * 128;
            cp16(dbase + O_A + row * (OLDK * 2) + lseg * 16,
                 srcA + (size_t)row * (HID * 2) + k0 * 2 + lseg * 16);
        }
        {
            int row = lrow;
            cp16(dbase + O_B + row * (OLDK * 2) + lseg * 16,
                 srcB + (size_t)row * (HID * 2) + k0 * 2 + lseg * 16);
        }
    };

    int mwarp = (warp >> 2) * 64;
    int nwarp = (warp & 3) * 32;

    float acc[4][4][4];
#pragma unroll
    for (int mi = 0; mi < 4; mi++)
#pragma unroll
        for (int nf = 0; nf < 4; nf++)
#pragma unroll
            for (int q = 0; q < 4; q++) acc[mi][nf][q] = 0.f;

    int flrow = lane & 7, mat = lane >> 3;
    int frow = (mat & 1) * 8 + flrow;
    int fk   = (mat >> 1) * 8;

    if (tid < 128) colsq[tid] = 0.f;

    load_stage(0, 0);
    CP_COMMIT();

    for (int kt = 0; kt < 16; kt++) {
        if (kt < 15) {
            load_stage((kt + 1) & 1, (kt + 1) * 32);
            CP_COMMIT();
            CP_WAIT1();
        } else {
            CP_WAIT0();
        }
        __syncthreads();
        uint32_t stb = sb + (kt & 1) * OSTAGE;

#pragma unroll
        for (int ks = 0; ks < 2; ks++) {
            int kk = ks * 16 + fk;
            uint32_t fa[4][4], fb[2][4];
#pragma unroll
            for (int mi = 0; mi < 4; mi++)
                ldm4(fa[mi], stb + O_A +
                     (uint32_t)((mwarp + mi * 16 + frow) * (OLDK * 2) + kk * 2));
#pragma unroll
            for (int nb = 0; nb < 2; nb++)
                ldm4(fb[nb], stb + O_B +
                     (uint32_t)((nwarp + nb * 16 + frow) * (OLDK * 2) + kk * 2));
#pragma unroll
            for (int mi = 0; mi < 4; mi++)
#pragma unroll
                for (int nf = 0; nf < 4; nf++) {
                    int nb = nf >> 1, hi = nf & 1;
                    mma_f16(acc[mi][nf], fa[mi], fb[nb][hi], fb[nb][hi + 2]);
                }
        }
        __syncthreads();
    }

    float cs0[4], cs1[4];
#pragma unroll
    for (int nf = 0; nf < 4; nf++) { cs0[nf] = 0.f; cs1[nf] = 0.f; }
#pragma unroll
    for (int mi = 0; mi < 4; mi++) {
        int row = mwarp + mi * 16 + (lane >> 2);
        float bi0 = bias[row], bi1 = bias[row + 8];
#pragma unroll
        for (int nf = 0; nf < 4; nf++) {
            acc[mi][nf][0] += bi0;
            acc[mi][nf][1] += bi0;
            acc[mi][nf][2] += bi1;
            acc[mi][nf][3] += bi1;
            cs0[nf] += acc[mi][nf][0] * acc[mi][nf][0] + acc[mi][nf][2] * acc[mi][nf][2];
            cs1[nf] += acc[mi][nf][1] * acc[mi][nf][1] + acc[mi][nf][3] * acc[mi][nf][3];
        }
    }
#pragma unroll
    for (int nf = 0; nf < 4; nf++) {
#pragma unroll
        for (int o = 4; o < 32; o <<= 1) {
            cs0[nf] += __shfl_xor_sync(0xFFFFFFFFu, cs0[nf], o);
            cs1[nf] += __shfl_xor_sync(0xFFFFFFFFu, cs1[nf], o);
        }
    }
    if (lane < 4) {
#pragma unroll
        for (int nf = 0; nf < 4; nf++) {
            int col = nwarp + nf * 8 + lane * 2;
            atomicAdd(&colsq[col], cs0[nf]);
            atomicAdd(&colsq[col + 1], cs1[nf]);
        }
    }
    __syncthreads();
    if (tid < 128) invs[tid] = 16.0f / fmaxf(sqrtf(colsq[tid]), 1e-12f);
    __syncthreads();

    float* ob = out + (size_t)b * CIN * HW + pos0;
#pragma unroll
    for (int mi = 0; mi < 4; mi++) {
        int row = mwarp + mi * 16 + (lane >> 2);
        float gr0 = gout[row], gr1 = gout[row + 8];
#pragma unroll
        for (int nf = 0; nf < 4; nf++) {
            int col = nwarp + nf * 8 + (lane & 3) * 2;
            float i0 = invs[col], i1 = invs[col + 1];
            *(float2*)(ob + (size_t)row * HW + col) =
                make_float2(acc[mi][nf][0] * i0 * gr0, acc[mi][nf][1] * i1 * gr0);
            *(float2*)(ob + (size_t)(row + 8) * HW + col) =
                make_float2(acc[mi][nf][2] * i0 * gr1, acc[mi][nf][3] * i1 * gr1);
        }
    }
}

// ---------------------------------------------------------------------------
extern "C" void kernel_launch(void* const* d_in, const int* in_sizes, int n_in,
                              void* d_out, int out_size) {
    const float* x      = (const float*)d_in[0];
    const float* g_in   = (const float*)d_in[1];
    const float* w_qkv  = (const float*)d_in[2];
    const float* mem_kv = (const float*)d_in[3];
    const float* w_out  = (const float*)d_in[4];
    const float* b_out  = (const float*)d_in[5];
    const float* g_out  = (const float*)d_in[6];
    float* out = (float*)d_out;

    float *rmax_ptr, *rinv_ptr, *part_ptr, *ctx_ptr;
    __half *w1_ptr, *wo1_ptr, *x1_ptr, *qkv_ptr, *ek_ptr, *a1_ptr;
    cudaGetSymbolAddress((void**)&w1_ptr,   g_w1);
    cudaGetSymbolAddress((void**)&wo1_ptr,  g_wo1);
    cudaGetSymbolAddress((void**)&x1_ptr,   g_x1);
    cudaGetSymbolAddress((void**)&qkv_ptr,  g_qkv);
    cudaGetSymbolAddress((void**)&ek_ptr,   g_ek);
    cudaGetSymbolAddress((void**)&rmax_ptr, g_rmax);
    cudaGetSymbolAddress((void**)&rinv_ptr, g_rinv);
    cudaGetSymbolAddress((void**)&part_ptr, g_part);
    cudaGetSymbolAddress((void**)&ctx_ptr,  g_ctx);
    cudaGetSymbolAddress((void**)&a1_ptr,   g_a1);

    cudaFuncSetAttribute(qkv_mma_kernel,
                         cudaFuncAttributeMaxDynamicSharedMemorySize, QSMTOT);
    cudaFuncSetAttribute(outnorm_mma_kernel,
                         cudaFuncAttributeMaxDynamicSharedMemorySize, OSMTOT);

    wconv_kernel<<<(O3 * CIN + 255) / 256, 256>>>(w_qkv, g_in, w1_ptr);
    woconv_kernel<<<(CIN * HID + 255) / 256, 256>>>(w_out, wo1_ptr);
    xnorm_kernel<<<dim3(HW / 32, BATCH), 256>>>(x, x1_ptr);
    qkv_mma_kernel<<<dim3(HW / 128, O3 / 256, BATCH), 512, QSMTOT>>>(
        w1_ptr, x1_ptr, qkv_ptr);
    kstats_kernel<<<dim3(HD, NH, BATCH), 256>>>(qkv_ptr, mem_kv, rmax_ptr, rinv_ptr, ek_ptr);
    ctxpart_kernel<<<dim3(NC, NH, BATCH), 256>>>(ek_ptr, qkv_ptr, part_ptr);
    ctxreduce_kernel<<<dim3(NH, BATCH), 256>>>(part_ptr, mem_kv, rmax_ptr, rinv_ptr, ctx_ptr);
    attend_kernel<<<dim3(HW / 64, NH, BATCH), 256>>>(qkv_ptr, ctx_ptr, a1_ptr);
    outnorm_mma_kernel<<<dim3(HW / 128, BATCH), 512, OSMTOT>>>(
        wo1_ptr, a1_ptr, b_out, g_out, out);
}

// round 15
// speedup vs baseline: 1.0648x; 1.0648x over previous
#include <cuda_runtime.h>
#include <cuda_fp16.h>
#include <math.h>
#include <stdint.h>
#include <string.h>

// Problem constants
#define BATCH 16
#define CIN   256
#define HW    4096
#define O3    1536
#define HID   512
#define NH    8
#define HD    64
#define NMEM  4
#define NC    8
#define CHUNK 512

// Scratch (device globals — allocation-free rule)
__device__ __half g_w1[O3 * CIN];
__device__ __half g_wo1[CIN * HID];
__device__ __half g_x1[(size_t)BATCH * HW * CIN];   // transposed [b][n][c], fp16
__device__ __half g_qkv[(size_t)BATCH * O3 * HW];   // 201 MB, fp16
__device__ __half g_ek[(size_t)BATCH * NH * HD * HW]; // exp(K-rmax)*rinv, fp16
__device__ float g_rmax[BATCH * NH * HD];
__device__ float g_rinv[BATCH * NH * HD];
__device__ float g_part[(size_t)NC * BATCH * NH * HD * HD];
__device__ float g_ctx[BATCH * NH * HD * HD];
__device__ __half g_a1[(size_t)BATCH * HW * HID];   // att^T [b][pos][hid], fp16

// ---- mma.sync helpers ------------------------------------------------------
__device__ __forceinline__ uint32_t smem_u32(const void* p) {
    uint32_t a;
    asm("{ .reg .u64 t; cvta.to.shared.u64 t, %1; cvt.u32.u64 %0, t; }"
        : "=r"(a) : "l"(p));
    return a;
}
__device__ __forceinline__ void ldm4(uint32_t* r, uint32_t addr) {
    asm volatile("ldmatrix.sync.aligned.m8n8.x4.shared.b16 {%0,%1,%2,%3}, [%4];"
                 : "=r"(r[0]), "=r"(r[1]), "=r"(r[2]), "=r"(r[3]) : "r"(addr));
}
__device__ __forceinline__ void mma_f16(float* c, const uint32_t* a,
                                        uint32_t b0, uint32_t b1) {
    asm volatile(
        "mma.sync.aligned.m16n8k16.row.col.f32.f16.f16.f32 "
        "{%0,%1,%2,%3}, {%4,%5,%6,%7}, {%8,%9}, {%0,%1,%2,%3};"
        : "+f"(c[0]), "+f"(c[1]), "+f"(c[2]), "+f"(c[3])
        : "r"(a[0]), "r"(a[1]), "r"(a[2]), "r"(a[3]), "r"(b0), "r"(b1));
}
__device__ __forceinline__ void cp16(uint32_t dst, const void* src) {
    asm volatile("cp.async.cg.shared.global [%0], [%1], 16;"
                 :: "r"(dst), "l"(src));
}
#define CP_COMMIT() asm volatile("cp.async.commit_group;" ::: "memory")
#define CP_WAIT2()  asm volatile("cp.async.wait_group 2;" ::: "memory")
#define CP_WAIT1()  asm volatile("cp.async.wait_group 1;" ::: "memory")
#define CP_WAIT0()  asm volatile("cp.async.wait_group 0;" ::: "memory")

__device__ __forceinline__ uint32_t pkh(float lo, float hi) {
    __half2 t = __floats2half2_rn(lo, hi);
    uint32_t r; memcpy(&r, &t, 4); return r;
}

// ---------------------------------------------------------------------------
// Kernel 1: fused rmsnorm-scale + transpose + fp16 convert.
// ---------------------------------------------------------------------------
__global__ __launch_bounds__(256) void xnorm_kernel(const float* __restrict__ x,
                                                    __half* __restrict__ x1) {
    int b = blockIdx.y;
    int n0 = blockIdx.x * 32;
    __shared__ float t[256][33];
    __shared__ float ps[8][33];
    __shared__ float sv[32];
    int tid = threadIdx.x;
    int tx = tid & 31, ty = tid >> 5;

    const float* xb = x + (size_t)b * CIN * HW + n0;
#pragma unroll
    for (int i = 0; i < 32; i++) {
        int c = ty + i * 8;
        t[c][tx] = xb[(size_t)c * HW + tx];
    }
    __syncthreads();
    {
        float a = 0.f;
#pragma unroll
        for (int j = 0; j < 32; j++) {
            float v = t[ty * 32 + j][tx];
            a += v * v;
        }
        ps[ty][tx] = a;
    }
    __syncthreads();
    if (tid < 32) {
        float a = 0.f;
#pragma unroll
        for (int g = 0; g < 8; g++) a += ps[g][tid];
        sv[tid] = 16.0f / fmaxf(sqrtf(a), 1e-12f);
    }
    __syncthreads();
#pragma unroll
    for (int cb = 0; cb < 4; cb++) {
#pragma unroll
        for (int i = 0; i < 4; i++) {
            int nr = ty + i * 8;
            int c0 = cb * 64 + tx * 2;
            float s = sv[nr];
            uint32_t h = pkh(t[c0][nr] * s, t[c0 + 1][nr] * s);
            *(uint32_t*)((char*)x1 +
                (((size_t)b * HW + n0 + nr) * CIN + c0) * 2) = h;
        }
    }
}

// ---------------------------------------------------------------------------
// Kernel 1b / 1b2: weight converts
// ---------------------------------------------------------------------------
__global__ __launch_bounds__(256) void wconv_kernel(const float* __restrict__ w,
                                                    const float* __restrict__ g,
                                                    __half* __restrict__ w1) {
    int i = blockIdx.x * 256 + threadIdx.x;
    if (i < O3 * CIN) w1[i] = __float2half_rn(w[i] * g[i & (CIN - 1)]);
}
__global__ __launch_bounds__(256) void woconv_kernel(const float* __restrict__ w,
                                                     __half* __restrict__ w1) {
    int i = blockIdx.x * 256 + threadIdx.x;
    if (i < CIN * HID) w1[i] = __float2half_rn(w[i]);
}

// ---------------------------------------------------------------------------
// Kernel 2: QKV GEMM, mma.sync fp16, fp16 out. CTA 128x128, K-tile 32,
// LDK=40, THREE-stage cp.async pipeline (60KB/CTA -> 2 CTAs/SM).
// 8 warps (4m x 2n), warp tile 32x64.
// ---------------------------------------------------------------------------
#define QLDK   40
#define QT_B   (128 * QLDK * 2)        // 10240 per tile
#define QSTAGE (2 * QT_B)              // 20480  (A, B)
#define QSMTOT (3 * QSTAGE)            // 61440  (3 stages)
#define Q_A    0
#define Q_B    QT_B

__global__ void __launch_bounds__(256, 2)
qkv_mma_kernel(const __half* __restrict__ w1,
               const __half* __restrict__ x1,
               __half* __restrict__ out) {
    extern __shared__ char smem[];
    uint32_t sb = smem_u32(smem);
    int tid = threadIdx.x;
    int warp = tid >> 5, lane = tid & 31;
    int b = blockIdx.z;
    int rowBase = blockIdx.y * 128;
    int colBase = blockIdx.x * 128;

    const char* srcA = (const char*)(w1 + (size_t)rowBase * CIN);
    const char* srcB = (const char*)(x1 + ((size_t)b * HW + colBase) * CIN);

    int lrow = tid >> 2, lseg = tid & 3;   // 64 rows x 4 segs (32 k = 64B)

    auto load_stage = [&](int st, int k0) {
        uint32_t dbase = sb + st * QSTAGE;
#pragma unroll
        for (int j = 0; j < 2; j++) {
            int row = lrow + j * 64;
            uint32_t dp = dbase + row * (QLDK * 2) + lseg * 16;
            size_t go = (size_t)row * (CIN * 2) + k0 * 2 + lseg * 16;
            cp16(dp + Q_A, srcA + go);
            cp16(dp + Q_B, srcB + go);
        }
    };

    int mwarp = (warp >> 1) * 32;
    int nwarp = (warp & 1) * 64;

    float acc[2][8][4];
#pragma unroll
    for (int mi = 0; mi < 2; mi++)
#pragma unroll
        for (int nf = 0; nf < 8; nf++)
#pragma unroll
            for (int q = 0; q < 4; q++) acc[mi][nf][q] = 0.f;

    int flrow = lane & 7, mat = lane >> 3;
    int frow = (mat & 1) * 8 + flrow;
    int fk   = (mat >> 1) * 8;

    load_stage(0, 0);
    CP_COMMIT();
    load_stage(1, 32);
    CP_COMMIT();

    for (int kt = 0; kt < 8; kt++) {
        if (kt < 6) {
            load_stage((kt + 2) % 3, (kt + 2) * 32);
            CP_COMMIT();
            CP_WAIT2();
        } else if (kt == 6) {
            CP_WAIT1();
        } else {
            CP_WAIT0();
        }
        __syncthreads();
        uint32_t stb = sb + (kt % 3) * QSTAGE;

#pragma unroll
        for (int ks = 0; ks < 2; ks++) {
            int kk = ks * 16 + fk;
            uint32_t fa[2][4], fb[4][4];
#pragma unroll
            for (int mi = 0; mi < 2; mi++)
                ldm4(fa[mi], stb + Q_A +
                     (uint32_t)((mwarp + mi * 16 + frow) * (QLDK * 2) + kk * 2));
#pragma unroll
            for (int nb = 0; nb < 4; nb++)
                ldm4(fb[nb], stb + Q_B +
                     (uint32_t)((nwarp + nb * 16 + frow) * (QLDK * 2) + kk * 2));
#pragma unroll
            for (int mi = 0; mi < 2; mi++)
#pragma unroll
                for (int nf = 0; nf < 8; nf++) {
                    int nb = nf >> 1, hi = nf & 1;
                    mma_f16(acc[mi][nf], fa[mi], fb[nb][hi], fb[nb][hi + 2]);
                }
        }
        __syncthreads();
    }

    __half* obase = out + (size_t)b * O3 * HW;
#pragma unroll
    for (int mi = 0; mi < 2; mi++) {
        int row = rowBase + mwarp + mi * 16 + (lane >> 2);
#pragma unroll
        for (int nf = 0; nf < 8; nf++) {
            int col = colBase + nwarp + nf * 8 + (lane & 3) * 2;
            *(uint32_t*)((char*)obase + ((size_t)row * HW + col) * 2) =
                pkh(acc[mi][nf][0], acc[mi][nf][1]);
            *(uint32_t*)((char*)obase + ((size_t)(row + 8) * HW + col) * 2) =
                pkh(acc[mi][nf][2], acc[mi][nf][3]);
        }
    }
}

// ---------------------------------------------------------------------------
// Kernel 3a: k-softmax stats + write ek = exp(K-rmax)*rinv (fp16)
// ---------------------------------------------------------------------------
__global__ __launch_bounds__(256) void kstats_kernel(const __half* __restrict__ qkv,
                                                     const float* __restrict__ memkv,
                                                     float* __restrict__ rmax,
                                                     float* __restrict__ rinv,
                                                     __half* __restrict__ ek) {
    int d = blockIdx.x, h = blockIdx.y, b = blockIdx.z;
    int tid = threadIdx.x;
    const __half2* kr = (const __half2*)(qkv + ((size_t)b * O3 + HID + h * HD + d) * HW);
    const float* MK = memkv + ((size_t)h * HD + d) * NMEM;

    float v[16];
#pragma unroll
    for (int i = 0; i < 8; i++) {
        float2 p = __half22float2(kr[i * 256 + tid]);
        v[2 * i] = p.x;
        v[2 * i + 1] = p.y;
    }
    float m = v[0];
#pragma unroll
    for (int i = 1; i < 16; i++) m = fmaxf(m, v[i]);
    if (tid < NMEM) m = fmaxf(m, MK[tid]);

    __shared__ float red[8];
#pragma unroll
    for (int o = 16; o; o >>= 1) m = fmaxf(m, __shfl_xor_sync(0xFFFFFFFFu, m, o));
    if ((tid & 31) == 0) red[tid >> 5] = m;
    __syncthreads();
    if (tid == 0) {
        float t = red[0];
#pragma unroll
        for (int i = 1; i < 8; i++) t = fmaxf(t, red[i]);
        red[0] = t;
    }
    __syncthreads();
    m = red[0];
    __syncthreads();

    float ss = 0.f;
#pragma unroll
    for (int i = 0; i < 16; i++) ss += __expf(v[i] - m);
    if (tid < NMEM) ss += __expf(MK[tid] - m);
#pragma unroll
    for (int o = 16; o; o >>= 1) ss += __shfl_xor_sync(0xFFFFFFFFu, ss, o);
    if ((tid & 31) == 0) red[tid >> 5] = ss;
    __syncthreads();
    if (tid == 0) {
        float t = 0.f;
#pragma unroll
        for (int i = 0; i < 8; i++) t += red[i];
        float rv = 1.0f / t;
        int idx = (b * NH + h) * HD + d;
        rmax[idx] = m;
        rinv[idx] = rv;
        red[0] = rv;
    }
    __syncthreads();
    float rv = red[0];
    __half2* ekw = (__half2*)(ek + ((size_t)(b * NH + h) * HD + d) * HW);
#pragma unroll
    for (int i = 0; i < 8; i++)
        ekw[i * 256 + tid] = __floats2half2_rn(__expf(v[2 * i] - m) * rv,
                                               __expf(v[2 * i + 1] - m) * rv);
}

// ---------------------------------------------------------------------------
// Kernel 3b: partial context via mma.sync fp16. M=64, N=64, K=512.
// ---------------------------------------------------------------------------
#define CLDK 72
#define CT_T (64 * CLDK * 2)
#define CSTAGE (2 * CT_T)

__global__ __launch_bounds__(256) void ctxpart_kernel(const __half* __restrict__ ek,
                                                      const __half* __restrict__ qkv,
                                                      float* __restrict__ part) {
    __shared__ __align__(16) char csm[2 * CSTAGE];
    uint32_t sb = smem_u32(csm);
    int tid = threadIdx.x, warp = tid >> 5, lane = tid & 31;
    int c = blockIdx.x, h = blockIdx.y, b = blockIdx.z;

    const char* srcA = (const char*)(ek + ((size_t)(b * NH + h) * HD) * HW + c * CHUNK);
    const char* srcB = (const char*)(qkv + ((size_t)b * O3 + 2 * HID + h * HD) * HW + c * CHUNK);

    int lrow = tid >> 3, lseg = tid & 7;

    auto load_stage = [&](int st, int n0) {
        uint32_t dbase = sb + st * CSTAGE;
#pragma unroll
        for (int j = 0; j < 2; j++) {
            int row = lrow + j * 32;
            uint32_t dp = dbase + row * (CLDK * 2) + lseg * 16;
            size_t go = ((size_t)row * HW + n0) * 2 + lseg * 16;
            cp16(dp, srcA + go);
            cp16(dp + CT_T, srcB + go);
        }
    };

    int mwarp = (warp >> 2) * 32;
    int nwarp = (warp & 3) * 16;

    float acc[2][2][4];
#pragma unroll
    for (int mi = 0; mi < 2; mi++)
#pragma unroll
        for (int nf = 0; nf < 2; nf++)
#pragma unroll
            for (int q = 0; q < 4; q++) acc[mi][nf][q] = 0.f;

    int flrow = lane & 7, mat = lane >> 3;
    int frow = (mat & 1) * 8 + flrow;
    int fk   = (mat >> 1) * 8;

    load_stage(0, 0);
    CP_COMMIT();

    for (int kt = 0; kt < 8; kt++) {
        if (kt < 7) {
            load_stage((kt + 1) & 1, (kt + 1) * 64);
            CP_COMMIT();
            CP_WAIT1();
        } else {
            CP_WAIT0();
        }
        __syncthreads();
        uint32_t stb = sb + (kt & 1) * CSTAGE;

#pragma unroll
        for (int ks = 0; ks < 4; ks++) {
            int kk = ks * 16 + fk;
            uint32_t fa[2][4], fb[4];
#pragma unroll
            for (int mi = 0; mi < 2; mi++)
                ldm4(fa[mi], stb +
                     (uint32_t)((mwarp + mi * 16 + frow) * (CLDK * 2) + kk * 2));
            ldm4(fb, stb + CT_T +
                 (uint32_t)((nwarp + frow) * (CLDK * 2) + kk * 2));
#pragma unroll
            for (int mi = 0; mi < 2; mi++)
#pragma unroll
                for (int nf = 0; nf < 2; nf++)
                    mma_f16(acc[mi][nf], fa[mi], fb[nf], fb[nf + 2]);
        }
        __syncthreads();
    }

    float* pb = part + ((size_t)c * BATCH * NH + b * NH + h) * (HD * HD);
#pragma unroll
    for (int mi = 0; mi < 2; mi++) {
        int d = mwarp + mi * 16 + (lane >> 2);
#pragma unroll
        for (int nf = 0; nf < 2; nf++) {
            int e = nwarp + nf * 8 + (lane & 3) * 2;
            *(float2*)(&pb[d * HD + e]) = make_float2(acc[mi][nf][0], acc[mi][nf][1]);
            *(float2*)(&pb[(d + 8) * HD + e]) = make_float2(acc[mi][nf][2], acc[mi][nf][3]);
        }
    }
}

// ---------------------------------------------------------------------------
// Kernel 3c: reduce partials + mem-kv tail -> ctx
// ---------------------------------------------------------------------------
__global__ __launch_bounds__(256) void ctxreduce_kernel(const float* __restrict__ part,
                                                        const float* __restrict__ memkv,
                                                        const float* __restrict__ rmax,
                                                        const float* __restrict__ rinv,
                                                        float* __restrict__ ctx) {
    int h = blockIdx.x, b = blockIdx.y;
    __shared__ float mkx[64][4];
    __shared__ float mvs[64][4];
    int tid = threadIdx.x;
    {
        int d = tid >> 2, j = tid & 3;
        int idx = (b * NH + h) * HD + d;
        mkx[d][j] = __expf(memkv[((size_t)h * HD + d) * NMEM + j] - rmax[idx]) * rinv[idx];
        mvs[d][j] = memkv[(size_t)NH * HD * NMEM + ((size_t)h * HD + d) * NMEM + j];
    }
    __syncthreads();
    size_t base = (size_t)(b * NH + h) * (HD * HD);
    for (int l = tid; l < HD * HD; l += 256) {
        int d = l >> 6, e = l & 63;
        float s2 = 0.f;
#pragma unroll
        for (int cc = 0; cc < NC; cc++)
            s2 += part[(size_t)cc * BATCH * NH * HD * HD + base + l];
#pragma unroll
        for (int j = 0; j < 4; j++) s2 += mkx[d][j] * mvs[e][j];
        ctx[base + l] = s2;
    }
}

// ---------------------------------------------------------------------------
// Kernel 4: q-softmax + tensorized 64x64x64 GEMM.
// ---------------------------------------------------------------------------
__global__ __launch_bounds__(256) void attend_kernel(const __half* __restrict__ qkv,
                                                     const float* __restrict__ ctx,
                                                     __half* __restrict__ a1) {
    int pos0 = blockIdx.x * 64;
    int h = blockIdx.y, b = blockIdx.z;
    const __half* Q = qkv + ((size_t)b * O3 + h * HD) * HW;
    const float* cb = ctx + (size_t)(b * NH + h) * HD * HD;

    __shared__ __align__(16) float qs[64][68];
    __shared__ __align__(16) __half cth[64][72];
    __shared__ __align__(16) __half qth[64][72];

    int tid = threadIdx.x, warp = tid >> 5, lane = tid & 31;

    for (int l = tid; l < 64 * 32; l += 256) {
        int d = l >> 5, p2 = (l & 31) * 2;
        float2 qv = __half22float2(*(const __half2*)(Q + (size_t)d * HW + pos0 + p2));
        qs[d][p2] = qv.x;
        qs[d][p2 + 1] = qv.y;
    }
    for (int l = tid; l < HD * HD; l += 256) {
        int d = l >> 6, e = l & 63;
        cth[e][d] = __float2half_rn(cb[l]);
    }
    __syncthreads();

    if (tid < 64) {
        float m = -1e30f;
#pragma unroll
        for (int d = 0; d < HD; d++) m = fmaxf(m, qs[d][tid]);
        float ss = 0.f;
#pragma unroll
        for (int d = 0; d < HD; d++) ss += __expf(qs[d][tid] - m);
        float inv = 0.125f / ss;
#pragma unroll
        for (int d = 0; d < HD; d++)
            qth[tid][d] = __float2half_rn(__expf(qs[d][tid] - m) * inv);
    }
    __syncthreads();

    int mwarp = (warp >> 2) * 32;
    int nwarp = (warp & 3) * 16;

    float acc[2][2][4];
#pragma unroll
    for (int mi = 0; mi < 2; mi++)
#pragma unroll
        for (int nf = 0; nf < 2; nf++)
#pragma unroll
            for (int q = 0; q < 4; q++) acc[mi][nf][q] = 0.f;

    int flrow = lane & 7, mat = lane >> 3;
    int frow = (mat & 1) * 8 + flrow;
    int fk   = (mat >> 1) * 8;

    uint32_t sc = smem_u32(cth), sq = smem_u32(qth);
#pragma unroll
    for (int ks = 0; ks < 4; ks++) {
        int kk = ks * 16 + fk;
        uint32_t fa[2][4], fb[4];
#pragma unroll
        for (int mi = 0; mi < 2; mi++)
            ldm4(fa[mi], sc + (uint32_t)((mwarp + mi * 16 + frow) * 144 + kk * 2));
        ldm4(fb, sq + (uint32_t)((nwarp + frow) * 144 + kk * 2));
#pragma unroll
        for (int mi = 0; mi < 2; mi++)
#pragma unroll
            for (int nf = 0; nf < 2; nf++)
                mma_f16(acc[mi][nf], fa[mi], fb[nf], fb[nf + 2]);
    }
    __syncthreads();

#pragma unroll
    for (int mi = 0; mi < 2; mi++) {
        int e = mwarp + mi * 16 + (lane >> 2);
#pragma unroll
        for (int nf = 0; nf < 2; nf++) {
            int p = nwarp + nf * 8 + (lane & 3) * 2;
            qth[p][e]         = __float2half_rn(acc[mi][nf][0]);
            qth[p + 1][e]     = __float2half_rn(acc[mi][nf][1]);
            qth[p][e + 8]     = __float2half_rn(acc[mi][nf][2]);
            qth[p + 1][e + 8] = __float2half_rn(acc[mi][nf][3]);
        }
    }
    __syncthreads();

    {
        int pos = tid >> 2, e0 = (tid & 3) * 16;
        size_t base = ((size_t)b * HW + pos0 + pos) * HID + h * HD + e0;
        uint32_t r[8];
#pragma unroll
        for (int u = 0; u < 8; u++)
            r[u] = *(const uint32_t*)(&qth[pos][e0 + 2 * u]);
        *(uint4*)((char*)a1 + base * 2)      = make_uint4(r[0], r[1], r[2], r[3]);
        *(uint4*)((char*)a1 + base * 2 + 16) = make_uint4(r[4], r[5], r[6], r[7]);
    }
}

// ---------------------------------------------------------------------------
// Kernel 5: out GEMM fp16 + bias + fused rmsnorm. CTA 256x128, K-tile 32,
// 512 thr / 16 warps (4m x 4n), warp tile 64x32.
// ---------------------------------------------------------------------------
#define OLDK   40
#define OA_T   (256 * OLDK * 2)
#define OB_T   (128 * OLDK * 2)
#define OSTAGE (OA_T + OB_T)
#define OSMTOT (2 * OSTAGE)
#define O_A    0
#define O_B    OA_T

__global__ void __launch_bounds__(512, 1)
outnorm_mma_kernel(const __half* __restrict__ wo1,
                   const __half* __restrict__ a1,
                   const float* __restrict__ bias,
                   const float* __restrict__ gout,
                   float* __restrict__ out) {
    extern __shared__ char smem[];
    uint32_t sb = smem_u32(smem);
    __shared__ float colsq[128];
    __shared__ float invs[128];

    int tid = threadIdx.x;
    int warp = tid >> 5, lane = tid & 31;
    int b = blockIdx.y;
    int pos0 = blockIdx.x * 128;

    const char* srcA = (const char*)wo1;
    const char* srcB = (const char*)(a1 + ((size_t)b * HW + pos0) * HID);

    int lrow = tid >> 2, lseg = tid & 3;

    auto load_stage = [&](int st, int k0) {
        uint32_t dbase = sb + st * OSTAGE;
#pragma unroll
        for (int j = 0; j < 2; j++) {
            int row = lrow + j * 128;
            cp16(dbase + O_A + row * (OLDK * 2) + lseg * 16,
                 srcA + (size_t)row * (HID * 2) + k0 * 2 + lseg * 16);
        }
        {
            int row = lrow;
            cp16(dbase + O_B + row * (OLDK * 2) + lseg * 16,
                 srcB + (size_t)row * (HID * 2) + k0 * 2 + lseg * 16);
        }
    };

    int mwarp = (warp >> 2) * 64;
    int nwarp = (warp & 3) * 32;

    float acc[4][4][4];
#pragma unroll
    for (int mi = 0; mi < 4; mi++)
#pragma unroll
        for (int nf = 0; nf < 4; nf++)
#pragma unroll
            for (int q = 0; q < 4; q++) acc[mi][nf][q] = 0.f;

    int flrow = lane & 7, mat = lane >> 3;
    int frow = (mat & 1) * 8 + flrow;
    int fk   = (mat >> 1) * 8;

    if (tid < 128) colsq[tid] = 0.f;

    load_stage(0, 0);
    CP_COMMIT();

    for (int kt = 0; kt < 16; kt++) {
        if (kt < 15) {
            load_stage((kt + 1) & 1, (kt + 1) * 32);
            CP_COMMIT();
            CP_WAIT1();
        } else {
            CP_WAIT0();
        }
        __syncthreads();
        uint32_t stb = sb + (kt & 1) * OSTAGE;

#pragma unroll
        for (int ks = 0; ks < 2; ks++) {
            int kk = ks * 16 + fk;
            uint32_t fa[4][4], fb[2][4];
#pragma unroll
            for (int mi = 0; mi < 4; mi++)
                ldm4(fa[mi], stb + O_A +
                     (uint32_t)((mwarp + mi * 16 + frow) * (OLDK * 2) + kk * 2));
#pragma unroll
            for (int nb = 0; nb < 2; nb++)
                ldm4(fb[nb], stb + O_B +
                     (uint32_t)((nwarp + nb * 16 + frow) * (OLDK * 2) + kk * 2));
#pragma unroll
            for (int mi = 0; mi < 4; mi++)
#pragma unroll
                for (int nf = 0; nf < 4; nf++) {
                    int nb = nf >> 1, hi = nf & 1;
                    mma_f16(acc[mi][nf], fa[mi], fb[nb][hi], fb[nb][hi + 2]);
                }
        }
        __syncthreads();
    }

    float cs0[4], cs1[4];
#pragma unroll
    for (int nf = 0; nf < 4; nf++) { cs0[nf] = 0.f; cs1[nf] = 0.f; }
#pragma unroll
    for (int mi = 0; mi < 4; mi++) {
        int row = mwarp + mi * 16 + (lane >> 2);
        float bi0 = bias[row], bi1 = bias[row + 8];
#pragma unroll
        for (int nf = 0; nf < 4; nf++) {
            acc[mi][nf][0] += bi0;
            acc[mi][nf][1] += bi0;
            acc[mi][nf][2] += bi1;
            acc[mi][nf][3] += bi1;
            cs0[nf] += acc[mi][nf][0] * acc[mi][nf][0] + acc[mi][nf][2] * acc[mi][nf][2];
            cs1[nf] += acc[mi][nf][1] * acc[mi][nf][1] + acc[mi][nf][3] * acc[mi][nf][3];
        }
    }
#pragma unroll
    for (int nf = 0; nf < 4; nf++) {
#pragma unroll
        for (int o = 4; o < 32; o <<= 1) {
            cs0[nf] += __shfl_xor_sync(0xFFFFFFFFu, cs0[nf], o);
            cs1[nf] += __shfl_xor_sync(0xFFFFFFFFu, cs1[nf], o);
        }
    }
    if (lane < 4) {
#pragma unroll
        for (int nf = 0; nf < 4; nf++) {
            int col = nwarp + nf * 8 + lane * 2;
            atomicAdd(&colsq[col], cs0[nf]);
            atomicAdd(&colsq[col + 1], cs1[nf]);
        }
    }
    __syncthreads();
    if (tid < 128) invs[tid] = 16.0f / fmaxf(sqrtf(colsq[tid]), 1e-12f);
    __syncthreads();

    float* ob = out + (size_t)b * CIN * HW + pos0;
#pragma unroll
    for (int mi = 0; mi < 4; mi++) {
        int row = mwarp + mi * 16 + (lane >> 2);
        float gr0 = gout[row], gr1 = gout[row + 8];
#pragma unroll
        for (int nf = 0; nf < 4; nf++) {
            int col = nwarp + nf * 8 + (lane & 3) * 2;
            float i0 = invs[col], i1 = invs[col + 1];
            *(float2*)(ob + (size_t)row * HW + col) =
                make_float2(acc[mi][nf][0] * i0 * gr0, acc[mi][nf][1] * i1 * gr0);
            *(float2*)(ob + (size_t)(row + 8) * HW + col) =
                make_float2(acc[mi][nf][2] * i0 * gr1, acc[mi][nf][3] * i1 * gr1);
        }
    }
}

// ---------------------------------------------------------------------------
extern "C" void kernel_launch(void* const* d_in, const int* in_sizes, int n_in,
                              void* d_out, int out_size) {
    const float* x      = (const float*)d_in[0];
    const float* g_in   = (const float*)d_in[1];
    const float* w_qkv  = (const float*)d_in[2];
    const float* mem_kv = (const float*)d_in[3];
    const float* w_out  = (const float*)d_in[4];
    const float* b_out  = (const float*)d_in[5];
    const float* g_out  = (const float*)d_in[6];
    float* out = (float*)d_out;

    float *rmax_ptr, *rinv_ptr, *part_ptr, *ctx_ptr;
    __half *w1_ptr, *wo1_ptr, *x1_ptr, *qkv_ptr, *ek_ptr, *a1_ptr;
    cudaGetSymbolAddress((void**)&w1_ptr,   g_w1);
    cudaGetSymbolAddress((void**)&wo1_ptr,  g_wo1);
    cudaGetSymbolAddress((void**)&x1_ptr,   g_x1);
    cudaGetSymbolAddress((void**)&qkv_ptr,  g_qkv);
    cudaGetSymbolAddress((void**)&ek_ptr,   g_ek);
    cudaGetSymbolAddress((void**)&rmax_ptr, g_rmax);
    cudaGetSymbolAddress((void**)&rinv_ptr, g_rinv);
    cudaGetSymbolAddress((void**)&part_ptr, g_part);
    cudaGetSymbolAddress((void**)&ctx_ptr,  g_ctx);
    cudaGetSymbolAddress((void**)&a1_ptr,   g_a1);

    cudaFuncSetAttribute(qkv_mma_kernel,
                         cudaFuncAttributeMaxDynamicSharedMemorySize, QSMTOT);
    cudaFuncSetAttribute(outnorm_mma_kernel,
                         cudaFuncAttributeMaxDynamicSharedMemorySize, OSMTOT);

    wconv_kernel<<<(O3 * CIN + 255) / 256, 256>>>(w_qkv, g_in, w1_ptr);
    woconv_kernel<<<(CIN * HID + 255) / 256, 256>>>(w_out, wo1_ptr);
    xnorm_kernel<<<dim3(HW / 32, BATCH), 256>>>(x, x1_ptr);
    qkv_mma_kernel<<<dim3(HW / 128, O3 / 128, BATCH), 256, QSMTOT>>>(
        w1_ptr, x1_ptr, qkv_ptr);
    kstats_kernel<<<dim3(HD, NH, BATCH), 256>>>(qkv_ptr, mem_kv, rmax_ptr, rinv_ptr, ek_ptr);
    ctxpart_kernel<<<dim3(NC, NH, BATCH), 256>>>(ek_ptr, qkv_ptr, part_ptr);
    ctxreduce_kernel<<<dim3(NH, BATCH), 256>>>(part_ptr, mem_kv, rmax_ptr, rinv_ptr, ctx_ptr);
    attend_kernel<<<dim3(HW / 64, NH, BATCH), 256>>>(qkv_ptr, ctx_ptr, a1_ptr);
    outnorm_mma_kernel<<<dim3(HW / 128, BATCH), 512, OSMTOT>>>(
        wo1_ptr, a1_ptr, b_out, g_out, out);
}

// round 16
// speedup vs baseline: 1.1101x; 1.0425x over previous
#include <cuda_runtime.h>
#include <cuda_fp16.h>
#include <math.h>
#include <stdint.h>
#include <string.h>

// Problem constants
#define BATCH 16
#define CIN   256
#define HW    4096
#define O3    1536
#define HID   512
#define NH    8
#define HD    64
#define NMEM  4
#define NC    8
#define CHUNK 512

// Scratch (device globals — allocation-free rule)
__device__ __half g_w1[O3 * CIN];
__device__ __half g_wo1[CIN * HID];
__device__ __half g_x1[(size_t)BATCH * HW * CIN];   // transposed [b][n][c], fp16
__device__ __half g_qkv[(size_t)BATCH * O3 * HW];   // 201 MB, fp16
__device__ __half g_ek[(size_t)BATCH * NH * HD * HW]; // exp(K-rmax)*rinv, fp16
__device__ float g_rmax[BATCH * NH * HD];
__device__ float g_rinv[BATCH * NH * HD];
__device__ float g_part[(size_t)NC * BATCH * NH * HD * HD];
__device__ float g_ctx[BATCH * NH * HD * HD];
__device__ __half g_a1[(size_t)BATCH * HW * HID];   // att^T [b][pos][hid], fp16

// ---- mma.sync helpers ------------------------------------------------------
__device__ __forceinline__ uint32_t smem_u32(const void* p) {
    uint32_t a;
    asm("{ .reg .u64 t; cvta.to.shared.u64 t, %1; cvt.u32.u64 %0, t; }"
        : "=r"(a) : "l"(p));
    return a;
}
__device__ __forceinline__ void ldm4(uint32_t* r, uint32_t addr) {
    asm volatile("ldmatrix.sync.aligned.m8n8.x4.shared.b16 {%0,%1,%2,%3}, [%4];"
                 : "=r"(r[0]), "=r"(r[1]), "=r"(r[2]), "=r"(r[3]) : "r"(addr));
}
__device__ __forceinline__ void mma_f16(float* c, const uint32_t* a,
                                        uint32_t b0, uint32_t b1) {
    asm volatile(
        "mma.sync.aligned.m16n8k16.row.col.f32.f16.f16.f32 "
        "{%0,%1,%2,%3}, {%4,%5,%6,%7}, {%8,%9}, {%0,%1,%2,%3};"
        : "+f"(c[0]), "+f"(c[1]), "+f"(c[2]), "+f"(c[3])
        : "r"(a[0]), "r"(a[1]), "r"(a[2]), "r"(a[3]), "r"(b0), "r"(b1));
}
__device__ __forceinline__ void cp16(uint32_t dst, const void* src) {
    asm volatile("cp.async.cg.shared.global [%0], [%1], 16;"
                 :: "r"(dst), "l"(src));
}
#define CP_COMMIT() asm volatile("cp.async.commit_group;" ::: "memory")
#define CP_WAIT1()  asm volatile("cp.async.wait_group 1;" ::: "memory")
#define CP_WAIT0()  asm volatile("cp.async.wait_group 0;" ::: "memory")

__device__ __forceinline__ uint32_t pkh(float lo, float hi) {
    __half2 t = __floats2half2_rn(lo, hi);
    uint32_t r; memcpy(&r, &t, 4); return r;
}

// ---------------------------------------------------------------------------
// Kernel 1: fused rmsnorm-scale + transpose + fp16 convert.
// ---------------------------------------------------------------------------
__global__ __launch_bounds__(256) void xnorm_kernel(const float* __restrict__ x,
                                                    __half* __restrict__ x1) {
    int b = blockIdx.y;
    int n0 = blockIdx.x * 32;
    __shared__ float t[256][33];
    __shared__ float ps[8][33];
    __shared__ float sv[32];
    int tid = threadIdx.x;
    int tx = tid & 31, ty = tid >> 5;

    const float* xb = x + (size_t)b * CIN * HW + n0;
#pragma unroll
    for (int i = 0; i < 32; i++) {
        int c = ty + i * 8;
        t[c][tx] = xb[(size_t)c * HW + tx];
    }
    __syncthreads();
    {
        float a = 0.f;
#pragma unroll
        for (int j = 0; j < 32; j++) {
            float v = t[ty * 32 + j][tx];
            a += v * v;
        }
        ps[ty][tx] = a;
    }
    __syncthreads();
    if (tid < 32) {
        float a = 0.f;
#pragma unroll
        for (int g = 0; g < 8; g++) a += ps[g][tid];
        sv[tid] = 16.0f / fmaxf(sqrtf(a), 1e-12f);
    }
    __syncthreads();
#pragma unroll
    for (int cb = 0; cb < 4; cb++) {
#pragma unroll
        for (int i = 0; i < 4; i++) {
            int nr = ty + i * 8;
            int c0 = cb * 64 + tx * 2;
            float s = sv[nr];
            uint32_t h = pkh(t[c0][nr] * s, t[c0 + 1][nr] * s);
            *(uint32_t*)((char*)x1 +
                (((size_t)b * HW + n0 + nr) * CIN + c0) * 2) = h;
        }
    }
}

// ---------------------------------------------------------------------------
// Kernel 1b / 1b2: weight converts
// ---------------------------------------------------------------------------
__global__ __launch_bounds__(256) void wconv_kernel(const float* __restrict__ w,
                                                    const float* __restrict__ g,
                                                    __half* __restrict__ w1) {
    int i = blockIdx.x * 256 + threadIdx.x;
    if (i < O3 * CIN) w1[i] = __float2half_rn(w[i] * g[i & (CIN - 1)]);
}
__global__ __launch_bounds__(256) void woconv_kernel(const float* __restrict__ w,
                                                     __half* __restrict__ w1) {
    int i = blockIdx.x * 256 + threadIdx.x;
    if (i < CIN * HID) w1[i] = __float2half_rn(w[i]);
}

// ---------------------------------------------------------------------------
// Kernel 2: QKV GEMM, mma.sync fp16. CTA 128x128, K-tile 32, LDK=40,
// 3-stage depth-2 pipeline with SINGLE barrier per k-tile (loads issued
// after the sync). 60KB/CTA -> 2 CTAs/SM. 8 warps (4m x 2n).
// ---------------------------------------------------------------------------
#define QLDK   40
#define QT_B   (128 * QLDK * 2)        // 10240 per tile
#define QSTAGE (2 * QT_B)              // 20480  (A, B)
#define QSMTOT (3 * QSTAGE)            // 61440
#define Q_A    0
#define Q_B    QT_B

__global__ void __launch_bounds__(256, 2)
qkv_mma_kernel(const __half* __restrict__ w1,
               const __half* __restrict__ x1,
               __half* __restrict__ out) {
    extern __shared__ char smem[];
    uint32_t sb = smem_u32(smem);
    int tid = threadIdx.x;
    int warp = tid >> 5, lane = tid & 31;
    int b = blockIdx.z;
    int rowBase = blockIdx.y * 128;
    int colBase = blockIdx.x * 128;

    const char* srcA = (const char*)(w1 + (size_t)rowBase * CIN);
    const char* srcB = (const char*)(x1 + ((size_t)b * HW + colBase) * CIN);

    int lrow = tid >> 2, lseg = tid & 3;   // 64 rows x 4 segs (32 k = 64B)

    auto load_stage = [&](int st, int k0) {
        uint32_t dbase = sb + st * QSTAGE;
#pragma unroll
        for (int j = 0; j < 2; j++) {
            int row = lrow + j * 64;
            uint32_t dp = dbase + row * (QLDK * 2) + lseg * 16;
            size_t go = (size_t)row * (CIN * 2) + k0 * 2 + lseg * 16;
            cp16(dp + Q_A, srcA + go);
            cp16(dp + Q_B, srcB + go);
        }
    };

    int mwarp = (warp >> 1) * 32;
    int nwarp = (warp & 1) * 64;

    float acc[2][8][4];
#pragma unroll
    for (int mi = 0; mi < 2; mi++)
#pragma unroll
        for (int nf = 0; nf < 8; nf++)
#pragma unroll
            for (int q = 0; q < 4; q++) acc[mi][nf][q] = 0.f;

    int flrow = lane & 7, mat = lane >> 3;
    int frow = (mat & 1) * 8 + flrow;
    int fk   = (mat >> 1) * 8;

    load_stage(0, 0);
    CP_COMMIT();
    load_stage(1, 32);
    CP_COMMIT();

    for (int kt = 0; kt < 8; kt++) {
        if (kt < 7) { CP_WAIT1(); } else { CP_WAIT0(); }
        __syncthreads();
        if (kt < 6) {
            load_stage((kt + 2) % 3, (kt + 2) * 32);
            CP_COMMIT();
        }
        uint32_t stb = sb + (kt % 3) * QSTAGE;

#pragma unroll
        for (int ks = 0; ks < 2; ks++) {
            int kk = ks * 16 + fk;
            uint32_t fa[2][4], fb[4][4];
#pragma unroll
            for (int mi = 0; mi < 2; mi++)
                ldm4(fa[mi], stb + Q_A +
                     (uint32_t)((mwarp + mi * 16 + frow) * (QLDK * 2) + kk * 2));
#pragma unroll
            for (int nb = 0; nb < 4; nb++)
                ldm4(fb[nb], stb + Q_B +
                     (uint32_t)((nwarp + nb * 16 + frow) * (QLDK * 2) + kk * 2));
#pragma unroll
            for (int mi = 0; mi < 2; mi++)
#pragma unroll
                for (int nf = 0; nf < 8; nf++) {
                    int nb = nf >> 1, hi = nf & 1;
                    mma_f16(acc[mi][nf], fa[mi], fb[nb][hi], fb[nb][hi + 2]);
                }
        }
    }

    __half* obase = out + (size_t)b * O3 * HW;
#pragma unroll
    for (int mi = 0; mi < 2; mi++) {
        int row = rowBase + mwarp + mi * 16 + (lane >> 2);
#pragma unroll
        for (int nf = 0; nf < 8; nf++) {
            int col = colBase + nwarp + nf * 8 + (lane & 3) * 2;
            *(uint32_t*)((char*)obase + ((size_t)row * HW + col) * 2) =
                pkh(acc[mi][nf][0], acc[mi][nf][1]);
            *(uint32_t*)((char*)obase + ((size_t)(row + 8) * HW + col) * 2) =
                pkh(acc[mi][nf][2], acc[mi][nf][3]);
        }
    }
}

// ---------------------------------------------------------------------------
// Kernel 3a: k-softmax stats + write ek = exp(K-rmax)*rinv (fp16)
// ---------------------------------------------------------------------------
__global__ __launch_bounds__(256) void kstats_kernel(const __half* __restrict__ qkv,
                                                     const float* __restrict__ memkv,
                                                     float* __restrict__ rmax,
                                                     float* __restrict__ rinv,
                                                     __half* __restrict__ ek) {
    int d = blockIdx.x, h = blockIdx.y, b = blockIdx.z;
    int tid = threadIdx.x;
    const __half2* kr = (const __half2*)(qkv + ((size_t)b * O3 + HID + h * HD + d) * HW);
    const float* MK = memkv + ((size_t)h * HD + d) * NMEM;

    float v[16];
#pragma unroll
    for (int i = 0; i < 8; i++) {
        float2 p = __half22float2(kr[i * 256 + tid]);
        v[2 * i] = p.x;
        v[2 * i + 1] = p.y;
    }
    float m = v[0];
#pragma unroll
    for (int i = 1; i < 16; i++) m = fmaxf(m, v[i]);
    if (tid < NMEM) m = fmaxf(m, MK[tid]);

    __shared__ float red[8];
#pragma unroll
    for (int o = 16; o; o >>= 1) m = fmaxf(m, __shfl_xor_sync(0xFFFFFFFFu, m, o));
    if ((tid & 31) == 0) red[tid >> 5] = m;
    __syncthreads();
    if (tid == 0) {
        float t = red[0];
#pragma unroll
        for (int i = 1; i < 8; i++) t = fmaxf(t, red[i]);
        red[0] = t;
    }
    __syncthreads();
    m = red[0];
    __syncthreads();

    float ss = 0.f;
#pragma unroll
    for (int i = 0; i < 16; i++) ss += __expf(v[i] - m);
    if (tid < NMEM) ss += __expf(MK[tid] - m);
#pragma unroll
    for (int o = 16; o; o >>= 1) ss += __shfl_xor_sync(0xFFFFFFFFu, ss, o);
    if ((tid & 31) == 0) red[tid >> 5] = ss;
    __syncthreads();
    if (tid == 0) {
        float t = 0.f;
#pragma unroll
        for (int i = 0; i < 8; i++) t += red[i];
        float rv = 1.0f / t;
        int idx = (b * NH + h) * HD + d;
        rmax[idx] = m;
        rinv[idx] = rv;
        red[0] = rv;
    }
    __syncthreads();
    float rv = red[0];
    __half2* ekw = (__half2*)(ek + ((size_t)(b * NH + h) * HD + d) * HW);
#pragma unroll
    for (int i = 0; i < 8; i++)
        ekw[i * 256 + tid] = __floats2half2_rn(__expf(v[2 * i] - m) * rv,
                                               __expf(v[2 * i + 1] - m) * rv);
}

// ---------------------------------------------------------------------------
// Kernel 3b: partial context via mma.sync fp16, 3-stage single-barrier
// pipeline (dynamic smem 54KB). M=64, N=64, K=512.
// ---------------------------------------------------------------------------
#define CLDK 72
#define CT_T (64 * CLDK * 2)     // 9216
#define CSTAGE (2 * CT_T)        // 18432
#define CSMTOT (3 * CSTAGE)      // 55296

__global__ __launch_bounds__(256) void ctxpart_kernel(const __half* __restrict__ ek,
                                                      const __half* __restrict__ qkv,
                                                      float* __restrict__ part) {
    extern __shared__ char csm[];
    uint32_t sb = smem_u32(csm);
    int tid = threadIdx.x, warp = tid >> 5, lane = tid & 31;
    int c = blockIdx.x, h = blockIdx.y, b = blockIdx.z;

    const char* srcA = (const char*)(ek + ((size_t)(b * NH + h) * HD) * HW + c * CHUNK);
    const char* srcB = (const char*)(qkv + ((size_t)b * O3 + 2 * HID + h * HD) * HW + c * CHUNK);

    int lrow = tid >> 3, lseg = tid & 7;

    auto load_stage = [&](int st, int n0) {
        uint32_t dbase = sb + st * CSTAGE;
#pragma unroll
        for (int j = 0; j < 2; j++) {
            int row = lrow + j * 32;
            uint32_t dp = dbase + row * (CLDK * 2) + lseg * 16;
            size_t go = ((size_t)row * HW + n0) * 2 + lseg * 16;
            cp16(dp, srcA + go);
            cp16(dp + CT_T, srcB + go);
        }
    };

    int mwarp = (warp >> 2) * 32;
    int nwarp = (warp & 3) * 16;

    float acc[2][2][4];
#pragma unroll
    for (int mi = 0; mi < 2; mi++)
#pragma unroll
        for (int nf = 0; nf < 2; nf++)
#pragma unroll
            for (int q = 0; q < 4; q++) acc[mi][nf][q] = 0.f;

    int flrow = lane & 7, mat = lane >> 3;
    int frow = (mat & 1) * 8 + flrow;
    int fk   = (mat >> 1) * 8;

    load_stage(0, 0);
    CP_COMMIT();
    load_stage(1, 64);
    CP_COMMIT();

    for (int kt = 0; kt < 8; kt++) {
        if (kt < 7) { CP_WAIT1(); } else { CP_WAIT0(); }
        __syncthreads();
        if (kt < 6) {
            load_stage((kt + 2) % 3, (kt + 2) * 64);
            CP_COMMIT();
        }
        uint32_t stb = sb + (kt % 3) * CSTAGE;

#pragma unroll
        for (int ks = 0; ks < 4; ks++) {
            int kk = ks * 16 + fk;
            uint32_t fa[2][4], fb[4];
#pragma unroll
            for (int mi = 0; mi < 2; mi++)
                ldm4(fa[mi], stb +
                     (uint32_t)((mwarp + mi * 16 + frow) * (CLDK * 2) + kk * 2));
            ldm4(fb, stb + CT_T +
                 (uint32_t)((nwarp + frow) * (CLDK * 2) + kk * 2));
#pragma unroll
            for (int mi = 0; mi < 2; mi++)
#pragma unroll
                for (int nf = 0; nf < 2; nf++)
                    mma_f16(acc[mi][nf], fa[mi], fb[nf], fb[nf + 2]);
        }
    }

    float* pb = part + ((size_t)c * BATCH * NH + b * NH + h) * (HD * HD);
#pragma unroll
    for (int mi = 0; mi < 2; mi++) {
        int d = mwarp + mi * 16 + (lane >> 2);
#pragma unroll
        for (int nf = 0; nf < 2; nf++) {
            int e = nwarp + nf * 8 + (lane & 3) * 2;
            *(float2*)(&pb[d * HD + e]) = make_float2(acc[mi][nf][0], acc[mi][nf][1]);
            *(float2*)(&pb[(d + 8) * HD + e]) = make_float2(acc[mi][nf][2], acc[mi][nf][3]);
        }
    }
}

// ---------------------------------------------------------------------------
// Kernel 3c: reduce partials + mem-kv tail -> ctx
// ---------------------------------------------------------------------------
__global__ __launch_bounds__(256) void ctxreduce_kernel(const float* __restrict__ part,
                                                        const float* __restrict__ memkv,
                                                        const float* __restrict__ rmax,
                                                        const float* __restrict__ rinv,
                                                        float* __restrict__ ctx) {
    int h = blockIdx.x, b = blockIdx.y;
    __shared__ float mkx[64][4];
    __shared__ float mvs[64][4];
    int tid = threadIdx.x;
    {
        int d = tid >> 2, j = tid & 3;
        int idx = (b * NH + h) * HD + d;
        mkx[d][j] = __expf(memkv[((size_t)h * HD + d) * NMEM + j] - rmax[idx]) * rinv[idx];
        mvs[d][j] = memkv[(size_t)NH * HD * NMEM + ((size_t)h * HD + d) * NMEM + j];
    }
    __syncthreads();
    size_t base = (size_t)(b * NH + h) * (HD * HD);
    for (int l = tid; l < HD * HD; l += 256) {
        int d = l >> 6, e = l & 63;
        float s2 = 0.f;
#pragma unroll
        for (int cc = 0; cc < NC; cc++)
            s2 += part[(size_t)cc * BATCH * NH * HD * HD + base + l];
#pragma unroll
        for (int j = 0; j < 4; j++) s2 += mkx[d][j] * mvs[e][j];
        ctx[base + l] = s2;
    }
}

// ---------------------------------------------------------------------------
// Kernel 4: q-softmax + tensorized 64x64x64 GEMM.
// ---------------------------------------------------------------------------
__global__ __launch_bounds__(256) void attend_kernel(const __half* __restrict__ qkv,
                                                     const float* __restrict__ ctx,
                                                     __half* __restrict__ a1) {
    int pos0 = blockIdx.x * 64;
    int h = blockIdx.y, b = blockIdx.z;
    const __half* Q = qkv + ((size_t)b * O3 + h * HD) * HW;
    const float* cb = ctx + (size_t)(b * NH + h) * HD * HD;

    __shared__ __align__(16) float qs[64][68];
    __shared__ __align__(16) __half cth[64][72];
    __shared__ __align__(16) __half qth[64][72];

    int tid = threadIdx.x, warp = tid >> 5, lane = tid & 31;

    for (int l = tid; l < 64 * 32; l += 256) {
        int d = l >> 5, p2 = (l & 31) * 2;
        float2 qv = __half22float2(*(const __half2*)(Q + (size_t)d * HW + pos0 + p2));
        qs[d][p2] = qv.x;
        qs[d][p2 + 1] = qv.y;
    }
    for (int l = tid; l < HD * HD; l += 256) {
        int d = l >> 6, e = l & 63;
        cth[e][d] = __float2half_rn(cb[l]);
    }
    __syncthreads();

    if (tid < 64) {
        float m = -1e30f;
#pragma unroll
        for (int d = 0; d < HD; d++) m = fmaxf(m, qs[d][tid]);
        float ss = 0.f;
#pragma unroll
        for (int d = 0; d < HD; d++) ss += __expf(qs[d][tid] - m);
        float inv = 0.125f / ss;
#pragma unroll
        for (int d = 0; d < HD; d++)
            qth[tid][d] = __float2half_rn(__expf(qs[d][tid] - m) * inv);
    }
    __syncthreads();

    int mwarp = (warp >> 2) * 32;
    int nwarp = (warp & 3) * 16;

    float acc[2][2][4];
#pragma unroll
    for (int mi = 0; mi < 2; mi++)
#pragma unroll
        for (int nf = 0; nf < 2; nf++)
#pragma unroll
            for (int q = 0; q < 4; q++) acc[mi][nf][q] = 0.f;

    int flrow = lane & 7, mat = lane >> 3;
    int frow = (mat & 1) * 8 + flrow;
    int fk   = (mat >> 1) * 8;

    uint32_t sc = smem_u32(cth), sq = smem_u32(qth);
#pragma unroll
    for (int ks = 0; ks < 4; ks++) {
        int kk = ks * 16 + fk;
        uint32_t fa[2][4], fb[4];
#pragma unroll
        for (int mi = 0; mi < 2; mi++)
            ldm4(fa[mi], sc + (uint32_t)((mwarp + mi * 16 + frow) * 144 + kk * 2));
        ldm4(fb, sq + (uint32_t)((nwarp + frow) * 144 + kk * 2));
#pragma unroll
        for (int mi = 0; mi < 2; mi++)
#pragma unroll
            for (int nf = 0; nf < 2; nf++)
                mma_f16(acc[mi][nf], fa[mi], fb[nf], fb[nf + 2]);
    }
    __syncthreads();

#pragma unroll
    for (int mi = 0; mi < 2; mi++) {
        int e = mwarp + mi * 16 + (lane >> 2);
#pragma unroll
        for (int nf = 0; nf < 2; nf++) {
            int p = nwarp + nf * 8 + (lane & 3) * 2;
            qth[p][e]         = __float2half_rn(acc[mi][nf][0]);
            qth[p + 1][e]     = __float2half_rn(acc[mi][nf][1]);
            qth[p][e + 8]     = __float2half_rn(acc[mi][nf][2]);
            qth[p + 1][e + 8] = __float2half_rn(acc[mi][nf][3]);
        }
    }
    __syncthreads();

    {
        int pos = tid >> 2, e0 = (tid & 3) * 16;
        size_t base = ((size_t)b * HW + pos0 + pos) * HID + h * HD + e0;
        uint32_t r[8];
#pragma unroll
        for (int u = 0; u < 8; u++)
            r[u] = *(const uint32_t*)(&qth[pos][e0 + 2 * u]);
        *(uint4*)((char*)a1 + base * 2)      = make_uint4(r[0], r[1], r[2], r[3]);
        *(uint4*)((char*)a1 + base * 2 + 16) = make_uint4(r[4], r[5], r[6], r[7]);
    }
}

// ---------------------------------------------------------------------------
// Kernel 5: out GEMM fp16 + bias + fused rmsnorm. CTA 256x128, K-tile 32,
// 512 thr / 16 warps (4m x 4n), 3-stage single-barrier pipeline.
// ---------------------------------------------------------------------------
#define OLDK   40
#define OA_T   (256 * OLDK * 2)
#define OB_T   (128 * OLDK * 2)
#define OSTAGE (OA_T + OB_T)           // 30720
#define OSMTOT (3 * OSTAGE)            // 92160
#define O_A    0
#define O_B    OA_T

__global__ void __launch_bounds__(512, 1)
outnorm_mma_kernel(const __half* __restrict__ wo1,
                   const __half* __restrict__ a1,
                   const float* __restrict__ bias,
                   const float* __restrict__ gout,
                   float* __restrict__ out) {
    extern __shared__ char smem[];
    uint32_t sb = smem_u32(smem);
    __shared__ float colsq[128];
    __shared__ float invs[128];

    int tid = threadIdx.x;
    int warp = tid >> 5, lane = tid & 31;
    int b = blockIdx.y;
    int pos0 = blockIdx.x * 128;

    const char* srcA = (const char*)wo1;
    const char* srcB = (const char*)(a1 + ((size_t)b * HW + pos0) * HID);

    int lrow = tid >> 2, lseg = tid & 3;

    auto load_stage = [&](int st, int k0) {
        uint32_t dbase = sb + st * OSTAGE;
#pragma unroll
        for (int j = 0; j < 2; j++) {
            int row = lrow + j * 128;
            cp16(dbase + O_A + row * (OLDK * 2) + lseg * 16,
                 srcA + (size_t)row * (HID * 2) + k0 * 2 + lseg * 16);
        }
        {
            int row = lrow;
            cp16(dbase + O_B + row * (OLDK * 2) + lseg * 16,
                 srcB + (size_t)row * (HID * 2) + k0 * 2 + lseg * 16);
        }
    };

    int mwarp = (warp >> 2) * 64;
    int nwarp = (warp & 3) * 32;

    float acc[4][4][4];
#pragma unroll
    for (int mi = 0; mi < 4; mi++)
#pragma unroll
        for (int nf = 0; nf < 4; nf++)
#pragma unroll
            for (int q = 0; q < 4; q++) acc[mi][nf][q] = 0.f;

    int flrow = lane & 7, mat = lane >> 3;
    int frow = (mat & 1) * 8 + flrow;
    int fk   = (mat >> 1) * 8;

    if (tid < 128) colsq[tid] = 0.f;

    load_stage(0, 0);
    CP_COMMIT();
    load_stage(1, 32);
    CP_COMMIT();

    for (int kt = 0; kt < 16; kt++) {
        if (kt < 15) { CP_WAIT1(); } else { CP_WAIT0(); }
        __syncthreads();
        if (kt < 14) {
            load_stage((kt + 2) % 3, (kt + 2) * 32);
            CP_COMMIT();
        }
        uint32_t stb = sb + (kt % 3) * OSTAGE;

#pragma unroll
        for (int ks = 0; ks < 2; ks++) {
            int kk = ks * 16 + fk;
            uint32_t fa[4][4], fb[2][4];
#pragma unroll
            for (int mi = 0; mi < 4; mi++)
                ldm4(fa[mi], stb + O_A +
                     (uint32_t)((mwarp + mi * 16 + frow) * (OLDK * 2) + kk * 2));
#pragma unroll
            for (int nb = 0; nb < 2; nb++)
                ldm4(fb[nb], stb + O_B +
                     (uint32_t)((nwarp + nb * 16 + frow) * (OLDK * 2) + kk * 2));
#pragma unroll
            for (int mi = 0; mi < 4; mi++)
#pragma unroll
                for (int nf = 0; nf < 4; nf++) {
                    int nb = nf >> 1, hi = nf & 1;
                    mma_f16(acc[mi][nf], fa[mi], fb[nb][hi], fb[nb][hi + 2]);
                }
        }
    }

    float cs0[4], cs1[4];
#pragma unroll
    for (int nf = 0; nf < 4; nf++) { cs0[nf] = 0.f; cs1[nf] = 0.f; }
#pragma unroll
    for (int mi = 0; mi < 4; mi++) {
        int row = mwarp + mi * 16 + (lane >> 2);
        float bi0 = bias[row], bi1 = bias[row + 8];
#pragma unroll
        for (int nf = 0; nf < 4; nf++) {
            acc[mi][nf][0] += bi0;
            acc[mi][nf][1] += bi0;
            acc[mi][nf][2] += bi1;
            acc[mi][nf][3] += bi1;
            cs0[nf] += acc[mi][nf][0] * acc[mi][nf][0] + acc[mi][nf][2] * acc[mi][nf][2];
            cs1[nf] += acc[mi][nf][1] * acc[mi][nf][1] + acc[mi][nf][3] * acc[mi][nf][3];
        }
    }
#pragma unroll
    for (int nf = 0; nf < 4; nf++) {
#pragma unroll
        for (int o = 4; o < 32; o <<= 1) {
            cs0[nf] += __shfl_xor_sync(0xFFFFFFFFu, cs0[nf], o);
            cs1[nf] += __shfl_xor_sync(0xFFFFFFFFu, cs1[nf], o);
        }
    }
    if (lane < 4) {
#pragma unroll
        for (int nf = 0; nf < 4; nf++) {
            int col = nwarp + nf * 8 + lane * 2;
            atomicAdd(&colsq[col], cs0[nf]);
            atomicAdd(&colsq[col + 1], cs1[nf]);
        }
    }
    __syncthreads();
    if (tid < 128) invs[tid] = 16.0f / fmaxf(sqrtf(colsq[tid]), 1e-12f);
    __syncthreads();

    float* ob = out + (size_t)b * CIN * HW + pos0;
#pragma unroll
    for (int mi = 0; mi < 4; mi++) {
        int row = mwarp + mi * 16 + (lane >> 2);
        float gr0 = gout[row], gr1 = gout[row + 8];
#pragma unroll
        for (int nf = 0; nf < 4; nf++) {
            int col = nwarp + nf * 8 + (lane & 3) * 2;
            float i0 = invs[col], i1 = invs[col + 1];
            *(float2*)(ob + (size_t)row * HW + col) =
                make_float2(acc[mi][nf][0] * i0 * gr0, acc[mi][nf][1] * i1 * gr0);
            *(float2*)(ob + (size_t)(row + 8) * HW + col) =
                make_float2(acc[mi][nf][2] * i0 * gr1, acc[mi][nf][3] * i1 * gr1);
        }
    }
}

// ---------------------------------------------------------------------------
extern "C" void kernel_launch(void* const* d_in, const int* in_sizes, int n_in,
                              void* d_out, int out_size) {
    const float* x      = (const float*)d_in[0];
    const float* g_in   = (const float*)d_in[1];
    const float* w_qkv  = (const float*)d_in[2];
    const float* mem_kv = (const float*)d_in[3];
    const float* w_out  = (const float*)d_in[4];
    const float* b_out  = (const float*)d_in[5];
    const float* g_out  = (const float*)d_in[6];
    float* out = (float*)d_out;

    float *rmax_ptr, *rinv_ptr, *part_ptr, *ctx_ptr;
    __half *w1_ptr, *wo1_ptr, *x1_ptr, *qkv_ptr, *ek_ptr, *a1_ptr;
    cudaGetSymbolAddress((void**)&w1_ptr,   g_w1);
    cudaGetSymbolAddress((void**)&wo1_ptr,  g_wo1);
    cudaGetSymbolAddress((void**)&x1_ptr,   g_x1);
    cudaGetSymbolAddress((void**)&qkv_ptr,  g_qkv);
    cudaGetSymbolAddress((void**)&ek_ptr,   g_ek);
    cudaGetSymbolAddress((void**)&rmax_ptr, g_rmax);
    cudaGetSymbolAddress((void**)&rinv_ptr, g_rinv);
    cudaGetSymbolAddress((void**)&part_ptr, g_part);
    cudaGetSymbolAddress((void**)&ctx_ptr,  g_ctx);
    cudaGetSymbolAddress((void**)&a1_ptr,   g_a1);

    cudaFuncSetAttribute(qkv_mma_kernel,
                         cudaFuncAttributeMaxDynamicSharedMemorySize, QSMTOT);
    cudaFuncSetAttribute(ctxpart_kernel,
                         cudaFuncAttributeMaxDynamicSharedMemorySize, CSMTOT);
    cudaFuncSetAttribute(outnorm_mma_kernel,
                         cudaFuncAttributeMaxDynamicSharedMemorySize, OSMTOT);

    wconv_kernel<<<(O3 * CIN + 255) / 256, 256>>>(w_qkv, g_in, w1_ptr);
    woconv_kernel<<<(CIN * HID + 255) / 256, 256>>>(w_out, wo1_ptr);
    xnorm_kernel<<<dim3(HW / 32, BATCH), 256>>>(x, x1_ptr);
    qkv_mma_kernel<<<dim3(HW / 128, O3 / 128, BATCH), 256, QSMTOT>>>(
        w1_ptr, x1_ptr, qkv_ptr);
    kstats_kernel<<<dim3(HD, NH, BATCH), 256>>>(qkv_ptr, mem_kv, rmax_ptr, rinv_ptr, ek_ptr);
    ctxpart_kernel<<<dim3(NC, NH, BATCH), 256, CSMTOT>>>(ek_ptr, qkv_ptr, part_ptr);
    ctxreduce_kernel<<<dim3(NH, BATCH), 256>>>(part_ptr, mem_kv, rmax_ptr, rinv_ptr, ctx_ptr);
    attend_kernel<<<dim3(HW / 64, NH, BATCH), 256>>>(qkv_ptr, ctx_ptr, a1_ptr);
    outnorm_mma_kernel<<<dim3(HW / 128, BATCH), 512, OSMTOT>>>(
        wo1_ptr, a1_ptr, b_out, g_out, out);
}

// round 17
// speedup vs baseline: 1.2230x; 1.1018x over previous
#include <cuda_runtime.h>
#include <cuda_fp16.h>
#include <math.h>
#include <stdint.h>
#include <string.h>

// Problem constants
#define BATCH 16
#define CIN   256
#define HW    4096
#define O3    1536
#define HID   512
#define NH    8
#define HD    64
#define NMEM  4
#define NC    8
#define CHUNK 512

// Scratch (device globals — allocation-free rule)
__device__ __half g_w1[O3 * CIN];
__device__ __half g_wo1[CIN * HID];
__device__ __half g_x1[(size_t)BATCH * HW * CIN];   // transposed [b][n][c], fp16
__device__ __half g_qkv[(size_t)BATCH * O3 * HW];   // 201 MB, fp16
__device__ __half g_ek[(size_t)BATCH * NH * HD * HW]; // exp(K-rmax)*rinv, fp16
__device__ float g_rmax[BATCH * NH * HD];
__device__ float g_rinv[BATCH * NH * HD];
__device__ float g_part[(size_t)NC * BATCH * NH * HD * HD];
__device__ float g_ctx[BATCH * NH * HD * HD];
__device__ __half g_a1[(size_t)BATCH * HW * HID];   // att^T [b][pos][hid], fp16

// ---- mma.sync helpers ------------------------------------------------------
__device__ __forceinline__ uint32_t smem_u32(const void* p) {
    uint32_t a;
    asm("{ .reg .u64 t; cvta.to.shared.u64 t, %1; cvt.u32.u64 %0, t; }"
        : "=r"(a) : "l"(p));
    return a;
}
__device__ __forceinline__ void ldm4(uint32_t* r, uint32_t addr) {
    asm volatile("ldmatrix.sync.aligned.m8n8.x4.shared.b16 {%0,%1,%2,%3}, [%4];"
                 : "=r"(r[0]), "=r"(r[1]), "=r"(r[2]), "=r"(r[3]) : "r"(addr));
}
__device__ __forceinline__ void mma_f16(float* c, const uint32_t* a,
                                        uint32_t b0, uint32_t b1) {
    asm volatile(
        "mma.sync.aligned.m16n8k16.row.col.f32.f16.f16.f32 "
        "{%0,%1,%2,%3}, {%4,%5,%6,%7}, {%8,%9}, {%0,%1,%2,%3};"
        : "+f"(c[0]), "+f"(c[1]), "+f"(c[2]), "+f"(c[3])
        : "r"(a[0]), "r"(a[1]), "r"(a[2]), "r"(a[3]), "r"(b0), "r"(b1));
}
__device__ __forceinline__ void cp16(uint32_t dst, const void* src) {
    asm volatile("cp.async.cg.shared.global [%0], [%1], 16;"
                 :: "r"(dst), "l"(src));
}
#define CP_COMMIT() asm volatile("cp.async.commit_group;" ::: "memory")
#define CP_WAIT1()  asm volatile("cp.async.wait_group 1;" ::: "memory")
#define CP_WAIT0()  asm volatile("cp.async.wait_group 0;" ::: "memory")

__device__ __forceinline__ uint32_t pkh(float lo, float hi) {
    __half2 t = __floats2half2_rn(lo, hi);
    uint32_t r; memcpy(&r, &t, 4); return r;
}

// ---------------------------------------------------------------------------
// Kernel 1: fused rmsnorm-scale + transpose + fp16 convert.
// ---------------------------------------------------------------------------
__global__ __launch_bounds__(256) void xnorm_kernel(const float* __restrict__ x,
                                                    __half* __restrict__ x1) {
    int b = blockIdx.y;
    int n0 = blockIdx.x * 32;
    __shared__ float t[256][33];
    __shared__ float ps[8][33];
    __shared__ float sv[32];
    int tid = threadIdx.x;
    int tx = tid & 31, ty = tid >> 5;

    const float* xb = x + (size_t)b * CIN * HW + n0;
#pragma unroll
    for (int i = 0; i < 32; i++) {
        int c = ty + i * 8;
        t[c][tx] = xb[(size_t)c * HW + tx];
    }
    __syncthreads();
    {
        float a = 0.f;
#pragma unroll
        for (int j = 0; j < 32; j++) {
            float v = t[ty * 32 + j][tx];
            a += v * v;
        }
        ps[ty][tx] = a;
    }
    __syncthreads();
    if (tid < 32) {
        float a = 0.f;
#pragma unroll
        for (int g = 0; g < 8; g++) a += ps[g][tid];
        sv[tid] = 16.0f / fmaxf(sqrtf(a), 1e-12f);
    }
    __syncthreads();
#pragma unroll
    for (int cb = 0; cb < 4; cb++) {
#pragma unroll
        for (int i = 0; i < 4; i++) {
            int nr = ty + i * 8;
            int c0 = cb * 64 + tx * 2;
            float s = sv[nr];
            uint32_t h = pkh(t[c0][nr] * s, t[c0 + 1][nr] * s);
            *(uint32_t*)((char*)x1 +
                (((size_t)b * HW + n0 + nr) * CIN + c0) * 2) = h;
        }
    }
}

// ---------------------------------------------------------------------------
// Kernel 1b / 1b2: weight converts
// ---------------------------------------------------------------------------
__global__ __launch_bounds__(256) void wconv_kernel(const float* __restrict__ w,
                                                    const float* __restrict__ g,
                                                    __half* __restrict__ w1) {
    int i = blockIdx.x * 256 + threadIdx.x;
    if (i < O3 * CIN) w1[i] = __float2half_rn(w[i] * g[i & (CIN - 1)]);
}
__global__ __launch_bounds__(256) void woconv_kernel(const float* __restrict__ w,
                                                     __half* __restrict__ w1) {
    int i = blockIdx.x * 256 + threadIdx.x;
    if (i < CIN * HID) w1[i] = __float2half_rn(w[i]);
}

// ---------------------------------------------------------------------------
// Kernel 2: QKV GEMM, mma.sync fp16. CTA 128x128, K-tile 64, LDK=72,
// 3-stage single-barrier pipeline (110.6KB/CTA -> 2 CTAs/SM).
// 8 warps (4m x 2n), warp tile 32x64. 4 k-iterations.
// ---------------------------------------------------------------------------
#define QLDK   72
#define QT_B   (128 * QLDK * 2)        // 18432 per tile
#define QSTAGE (2 * QT_B)              // 36864  (A, B)
#define QSMTOT (3 * QSTAGE)            // 110592
#define Q_A    0
#define Q_B    QT_B

__global__ void __launch_bounds__(256, 2)
qkv_mma_kernel(const __half* __restrict__ w1,
               const __half* __restrict__ x1,
               __half* __restrict__ out) {
    extern __shared__ char smem[];
    uint32_t sb = smem_u32(smem);
    int tid = threadIdx.x;
    int warp = tid >> 5, lane = tid & 31;
    int b = blockIdx.z;
    int rowBase = blockIdx.y * 128;
    int colBase = blockIdx.x * 128;

    const char* srcA = (const char*)(w1 + (size_t)rowBase * CIN);
    const char* srcB = (const char*)(x1 + ((size_t)b * HW + colBase) * CIN);

    int lrow = tid >> 3, lseg = tid & 7;   // 32 rows x 8 segs (64 k = 128B)

    auto load_stage = [&](int st, int k0) {
        uint32_t dbase = sb + st * QSTAGE;
#pragma unroll
        for (int j = 0; j < 4; j++) {
            int row = lrow + j * 32;
            uint32_t dp = dbase + row * (QLDK * 2) + lseg * 16;
            size_t go = (size_t)row * (CIN * 2) + k0 * 2 + lseg * 16;
            cp16(dp + Q_A, srcA + go);
            cp16(dp + Q_B, srcB + go);
        }
    };

    int mwarp = (warp >> 1) * 32;
    int nwarp = (warp & 1) * 64;

    float acc[2][8][4];
#pragma unroll
    for (int mi = 0; mi < 2; mi++)
#pragma unroll
        for (int nf = 0; nf < 8; nf++)
#pragma unroll
            for (int q = 0; q < 4; q++) acc[mi][nf][q] = 0.f;

    int flrow = lane & 7, mat = lane >> 3;
    int frow = (mat & 1) * 8 + flrow;
    int fk   = (mat >> 1) * 8;

    load_stage(0, 0);
    CP_COMMIT();
    load_stage(1, 64);
    CP_COMMIT();

    for (int kt = 0; kt < 4; kt++) {
        if (kt < 3) { CP_WAIT1(); } else { CP_WAIT0(); }
        __syncthreads();
        if (kt < 2) {
            load_stage((kt + 2) % 3, (kt + 2) * 64);
            CP_COMMIT();
        }
        uint32_t stb = sb + (kt % 3) * QSTAGE;

#pragma unroll
        for (int ks = 0; ks < 4; ks++) {
            int kk = ks * 16 + fk;
            uint32_t fa[2][4], fb[4][4];
#pragma unroll
            for (int mi = 0; mi < 2; mi++)
                ldm4(fa[mi], stb + Q_A +
                     (uint32_t)((mwarp + mi * 16 + frow) * (QLDK * 2) + kk * 2));
#pragma unroll
            for (int nb = 0; nb < 4; nb++)
                ldm4(fb[nb], stb + Q_B +
                     (uint32_t)((nwarp + nb * 16 + frow) * (QLDK * 2) + kk * 2));
#pragma unroll
            for (int mi = 0; mi < 2; mi++)
#pragma unroll
                for (int nf = 0; nf < 8; nf++) {
                    int nb = nf >> 1, hi = nf & 1;
                    mma_f16(acc[mi][nf], fa[mi], fb[nb][hi], fb[nb][hi + 2]);
                }
        }
    }

    __half* obase = out + (size_t)b * O3 * HW;
#pragma unroll
    for (int mi = 0; mi < 2; mi++) {
        int row = rowBase + mwarp + mi * 16 + (lane >> 2);
#pragma unroll
        for (int nf = 0; nf < 8; nf++) {
            int col = colBase + nwarp + nf * 8 + (lane & 3) * 2;
            *(uint32_t*)((char*)obase + ((size_t)row * HW + col) * 2) =
                pkh(acc[mi][nf][0], acc[mi][nf][1]);
            *(uint32_t*)((char*)obase + ((size_t)(row + 8) * HW + col) * 2) =
                pkh(acc[mi][nf][2], acc[mi][nf][3]);
        }
    }
}

// ---------------------------------------------------------------------------
// Kernel 3a: k-softmax stats + write ek = exp(K-rmax)*rinv (fp16)
// ---------------------------------------------------------------------------
__global__ __launch_bounds__(256) void kstats_kernel(const __half* __restrict__ qkv,
                                                     const float* __restrict__ memkv,
                                                     float* __restrict__ rmax,
                                                     float* __restrict__ rinv,
                                                     __half* __restrict__ ek) {
    int d = blockIdx.x, h = blockIdx.y, b = blockIdx.z;
    int tid = threadIdx.x;
    const __half2* kr = (const __half2*)(qkv + ((size_t)b * O3 + HID + h * HD + d) * HW);
    const float* MK = memkv + ((size_t)h * HD + d) * NMEM;

    float v[16];
#pragma unroll
    for (int i = 0; i < 8; i++) {
        float2 p = __half22float2(kr[i * 256 + tid]);
        v[2 * i] = p.x;
        v[2 * i + 1] = p.y;
    }
    float m = v[0];
#pragma unroll
    for (int i = 1; i < 16; i++) m = fmaxf(m, v[i]);
    if (tid < NMEM) m = fmaxf(m, MK[tid]);

    __shared__ float red[8];
#pragma unroll
    for (int o = 16; o; o >>= 1) m = fmaxf(m, __shfl_xor_sync(0xFFFFFFFFu, m, o));
    if ((tid & 31) == 0) red[tid >> 5] = m;
    __syncthreads();
    if (tid == 0) {
        float t = red[0];
#pragma unroll
        for (int i = 1; i < 8; i++) t = fmaxf(t, red[i]);
        red[0] = t;
    }
    __syncthreads();
    m = red[0];
    __syncthreads();

    float ss = 0.f;
#pragma unroll
    for (int i = 0; i < 16; i++) ss += __expf(v[i] - m);
    if (tid < NMEM) ss += __expf(MK[tid] - m);
#pragma unroll
    for (int o = 16; o; o >>= 1) ss += __shfl_xor_sync(0xFFFFFFFFu, ss, o);
    if ((tid & 31) == 0) red[tid >> 5] = ss;
    __syncthreads();
    if (tid == 0) {
        float t = 0.f;
#pragma unroll
        for (int i = 0; i < 8; i++) t += red[i];
        float rv = 1.0f / t;
        int idx = (b * NH + h) * HD + d;
        rmax[idx] = m;
        rinv[idx] = rv;
        red[0] = rv;
    }
    __syncthreads();
    float rv = red[0];
    __half2* ekw = (__half2*)(ek + ((size_t)(b * NH + h) * HD + d) * HW);
#pragma unroll
    for (int i = 0; i < 8; i++)
        ekw[i * 256 + tid] = __floats2half2_rn(__expf(v[2 * i] - m) * rv,
                                               __expf(v[2 * i + 1] - m) * rv);
}

// ---------------------------------------------------------------------------
// Kernel 3b: partial context via mma.sync fp16, 3-stage single-barrier.
// ---------------------------------------------------------------------------
#define CLDK 72
#define CT_T (64 * CLDK * 2)     // 9216
#define CSTAGE (2 * CT_T)        // 18432
#define CSMTOT (3 * CSTAGE)      // 55296

__global__ __launch_bounds__(256) void ctxpart_kernel(const __half* __restrict__ ek,
                                                      const __half* __restrict__ qkv,
                                                      float* __restrict__ part) {
    extern __shared__ char csm[];
    uint32_t sb = smem_u32(csm);
    int tid = threadIdx.x, warp = tid >> 5, lane = tid & 31;
    int c = blockIdx.x, h = blockIdx.y, b = blockIdx.z;

    const char* srcA = (const char*)(ek + ((size_t)(b * NH + h) * HD) * HW + c * CHUNK);
    const char* srcB = (const char*)(qkv + ((size_t)b * O3 + 2 * HID + h * HD) * HW + c * CHUNK);

    int lrow = tid >> 3, lseg = tid & 7;

    auto load_stage = [&](int st, int n0) {
        uint32_t dbase = sb + st * CSTAGE;
#pragma unroll
        for (int j = 0; j < 2; j++) {
            int row = lrow + j * 32;
            uint32_t dp = dbase + row * (CLDK * 2) + lseg * 16;
            size_t go = ((size_t)row * HW + n0) * 2 + lseg * 16;
            cp16(dp, srcA + go);
            cp16(dp + CT_T, srcB + go);
        }
    };

    int mwarp = (warp >> 2) * 32;
    int nwarp = (warp & 3) * 16;

    float acc[2][2][4];
#pragma unroll
    for (int mi = 0; mi < 2; mi++)
#pragma unroll
        for (int nf = 0; nf < 2; nf++)
#pragma unroll
            for (int q = 0; q < 4; q++) acc[mi][nf][q] = 0.f;

    int flrow = lane & 7, mat = lane >> 3;
    int frow = (mat & 1) * 8 + flrow;
    int fk   = (mat >> 1) * 8;

    load_stage(0, 0);
    CP_COMMIT();
    load_stage(1, 64);
    CP_COMMIT();

    for (int kt = 0; kt < 8; kt++) {
        if (kt < 7) { CP_WAIT1(); } else { CP_WAIT0(); }
        __syncthreads();
        if (kt < 6) {
            load_stage((kt + 2) % 3, (kt + 2) * 64);
            CP_COMMIT();
        }
        uint32_t stb = sb + (kt % 3) * CSTAGE;

#pragma unroll
        for (int ks = 0; ks < 4; ks++) {
            int kk = ks * 16 + fk;
            uint32_t fa[2][4], fb[4];
#pragma unroll
            for (int mi = 0; mi < 2; mi++)
                ldm4(fa[mi], stb +
                     (uint32_t)((mwarp + mi * 16 + frow) * (CLDK * 2) + kk * 2));
            ldm4(fb, stb + CT_T +
                 (uint32_t)((nwarp + frow) * (CLDK * 2) + kk * 2));
#pragma unroll
            for (int mi = 0; mi < 2; mi++)
#pragma unroll
                for (int nf = 0; nf < 2; nf++)
                    mma_f16(acc[mi][nf], fa[mi], fb[nf], fb[nf + 2]);
        }
    }

    float* pb = part + ((size_t)c * BATCH * NH + b * NH + h) * (HD * HD);
#pragma unroll
    for (int mi = 0; mi < 2; mi++) {
        int d = mwarp + mi * 16 + (lane >> 2);
#pragma unroll
        for (int nf = 0; nf < 2; nf++) {
            int e = nwarp + nf * 8 + (lane & 3) * 2;
            *(float2*)(&pb[d * HD + e]) = make_float2(acc[mi][nf][0], acc[mi][nf][1]);
            *(float2*)(&pb[(d + 8) * HD + e]) = make_float2(acc[mi][nf][2], acc[mi][nf][3]);
        }
    }
}

// ---------------------------------------------------------------------------
// Kernel 3c: reduce partials + mem-kv tail -> ctx
// ---------------------------------------------------------------------------
__global__ __launch_bounds__(256) void ctxreduce_kernel(const float* __restrict__ part,
                                                        const float* __restrict__ memkv,
                                                        const float* __restrict__ rmax,
                                                        const float* __restrict__ rinv,
                                                        float* __restrict__ ctx) {
    int h = blockIdx.x, b = blockIdx.y;
    __shared__ float mkx[64][4];
    __shared__ float mvs[64][4];
    int tid = threadIdx.x;
    {
        int d = tid >> 2, j = tid & 3;
        int idx = (b * NH + h) * HD + d;
        mkx[d][j] = __expf(memkv[((size_t)h * HD + d) * NMEM + j] - rmax[idx]) * rinv[idx];
        mvs[d][j] = memkv[(size_t)NH * HD * NMEM + ((size_t)h * HD + d) * NMEM + j];
    }
    __syncthreads();
    size_t base = (size_t)(b * NH + h) * (HD * HD);
    for (int l = tid; l < HD * HD; l += 256) {
        int d = l >> 6, e = l & 63;
        float s2 = 0.f;
#pragma unroll
        for (int cc = 0; cc < NC; cc++)
            s2 += part[(size_t)cc * BATCH * NH * HD * HD + base + l];
#pragma unroll
        for (int j = 0; j < 4; j++) s2 += mkx[d][j] * mvs[e][j];
        ctx[base + l] = s2;
    }
}

// ---------------------------------------------------------------------------
// Kernel 4: q-softmax + tensorized GEMM; 128 positions per block (two
// 64-pos passes sharing one ctx load/convert).
// ---------------------------------------------------------------------------
__global__ __launch_bounds__(256) void attend_kernel(const __half* __restrict__ qkv,
                                                     const float* __restrict__ ctx,
                                                     __half* __restrict__ a1) {
    int posBase = blockIdx.x * 128;
    int h = blockIdx.y, b = blockIdx.z;
    const __half* Q = qkv + ((size_t)b * O3 + h * HD) * HW;
    const float* cb = ctx + (size_t)(b * NH + h) * HD * HD;

    __shared__ __align__(16) float qs[64][68];
    __shared__ __align__(16) __half cth[64][72];
    __shared__ __align__(16) __half qth[64][72];

    int tid = threadIdx.x, warp = tid >> 5, lane = tid & 31;

    for (int l = tid; l < HD * HD; l += 256) {
        int d = l >> 6, e = l & 63;
        cth[e][d] = __float2half_rn(cb[l]);
    }

    int mwarp = (warp >> 2) * 32;
    int nwarp = (warp & 3) * 16;
    int flrow = lane & 7, mat = lane >> 3;
    int frow = (mat & 1) * 8 + flrow;
    int fk   = (mat >> 1) * 8;
    uint32_t sc = smem_u32(cth), sq = smem_u32(qth);

#pragma unroll
    for (int half = 0; half < 2; half++) {
        int pos0 = posBase + half * 64;
        __syncthreads();
        for (int l = tid; l < 64 * 32; l += 256) {
            int d = l >> 5, p2 = (l & 31) * 2;
            float2 qv = __half22float2(*(const __half2*)(Q + (size_t)d * HW + pos0 + p2));
            qs[d][p2] = qv.x;
            qs[d][p2 + 1] = qv.y;
        }
        __syncthreads();

        if (tid < 64) {
            float m = -1e30f;
#pragma unroll
            for (int d = 0; d < HD; d++) m = fmaxf(m, qs[d][tid]);
            float ss = 0.f;
#pragma unroll
            for (int d = 0; d < HD; d++) ss += __expf(qs[d][tid] - m);
            float inv = 0.125f / ss;
#pragma unroll
            for (int d = 0; d < HD; d++)
                qth[tid][d] = __float2half_rn(__expf(qs[d][tid] - m) * inv);
        }
        __syncthreads();

        float acc[2][2][4];
#pragma unroll
        for (int mi = 0; mi < 2; mi++)
#pragma unroll
            for (int nf = 0; nf < 2; nf++)
#pragma unroll
                for (int q = 0; q < 4; q++) acc[mi][nf][q] = 0.f;

#pragma unroll
        for (int ks = 0; ks < 4; ks++) {
            int kk = ks * 16 + fk;
            uint32_t fa[2][4], fb[4];
#pragma unroll
            for (int mi = 0; mi < 2; mi++)
                ldm4(fa[mi], sc + (uint32_t)((mwarp + mi * 16 + frow) * 144 + kk * 2));
            ldm4(fb, sq + (uint32_t)((nwarp + frow) * 144 + kk * 2));
#pragma unroll
            for (int mi = 0; mi < 2; mi++)
#pragma unroll
                for (int nf = 0; nf < 2; nf++)
                    mma_f16(acc[mi][nf], fa[mi], fb[nf], fb[nf + 2]);
        }
        __syncthreads();

#pragma unroll
        for (int mi = 0; mi < 2; mi++) {
            int e = mwarp + mi * 16 + (lane >> 2);
#pragma unroll
            for (int nf = 0; nf < 2; nf++) {
                int p = nwarp + nf * 8 + (lane & 3) * 2;
                qth[p][e]         = __float2half_rn(acc[mi][nf][0]);
                qth[p + 1][e]     = __float2half_rn(acc[mi][nf][1]);
                qth[p][e + 8]     = __float2half_rn(acc[mi][nf][2]);
                qth[p + 1][e + 8] = __float2half_rn(acc[mi][nf][3]);
            }
        }
        __syncthreads();

        {
            int pos = tid >> 2, e0 = (tid & 3) * 16;
            size_t base = ((size_t)b * HW + pos0 + pos) * HID + h * HD + e0;
            uint32_t r[8];
#pragma unroll
            for (int u = 0; u < 8; u++)
                r[u] = *(const uint32_t*)(&qth[pos][e0 + 2 * u]);
            *(uint4*)((char*)a1 + base * 2)      = make_uint4(r[0], r[1], r[2], r[3]);
            *(uint4*)((char*)a1 + base * 2 + 16) = make_uint4(r[4], r[5], r[6], r[7]);
        }
    }
}

// ---------------------------------------------------------------------------
// Kernel 5: out GEMM fp16 + bias + fused rmsnorm. CTA 256x64, K-tile 32,
// 256 thr / 8 warps (4m x 2n), 3-stage single-barrier, 2 CTAs/SM.
// ---------------------------------------------------------------------------
#define OLDK   40
#define OA_T   (256 * OLDK * 2)        // 20480
#define OB_T   (64 * OLDK * 2)         // 5120
#define OSTAGE (OA_T + OB_T)           // 25600
#define OSMTOT (3 * OSTAGE)            // 76800
#define O_A    0
#define O_B    OA_T

__global__ void __launch_bounds__(256, 2)
outnorm_mma_kernel(const __half* __restrict__ wo1,
                   const __half* __restrict__ a1,
                   const float* __restrict__ bias,
                   const float* __restrict__ gout,
                   float* __restrict__ out) {
    extern __shared__ char smem[];
    uint32_t sb = smem_u32(smem);
    __shared__ float colsq[64];
    __shared__ float invs[64];

    int tid = threadIdx.x;
    int warp = tid >> 5, lane = tid & 31;
    int b = blockIdx.y;
    int pos0 = blockIdx.x * 64;

    const char* srcA = (const char*)wo1;
    const char* srcB = (const char*)(a1 + ((size_t)b * HW + pos0) * HID);

    int lrow = tid >> 2, lseg = tid & 3;

    auto load_stage = [&](int st, int k0) {
        uint32_t dbase = sb + st * OSTAGE;
#pragma unroll
        for (int j = 0; j < 4; j++) {
            int row = lrow + j * 64;
            cp16(dbase + O_A + row * (OLDK * 2) + lseg * 16,
                 srcA + (size_t)row * (HID * 2) + k0 * 2 + lseg * 16);
        }
        {
            int row = lrow;
            cp16(dbase + O_B + row * (OLDK * 2) + lseg * 16,
                 srcB + (size_t)row * (HID * 2) + k0 * 2 + lseg * 16);
        }
    };

    int mwarp = (warp >> 1) * 64;
    int nwarp = (warp & 1) * 32;

    float acc[4][4][4];
#pragma unroll
    for (int mi = 0; mi < 4; mi++)
#pragma unroll
        for (int nf = 0; nf < 4; nf++)
#pragma unroll
            for (int q = 0; q < 4; q++) acc[mi][nf][q] = 0.f;

    int flrow = lane & 7, mat = lane >> 3;
    int frow = (mat & 1) * 8 + flrow;
    int fk   = (mat >> 1) * 8;

    if (tid < 64) colsq[tid] = 0.f;

    load_stage(0, 0);
    CP_COMMIT();
    load_stage(1, 32);
    CP_COMMIT();

    for (int kt = 0; kt < 16; kt++) {
        if (kt < 15) { CP_WAIT1(); } else { CP_WAIT0(); }
        __syncthreads();
        if (kt < 14) {
            load_stage((kt + 2) % 3, (kt + 2) * 32);
            CP_COMMIT();
        }
        uint32_t stb = sb + (kt % 3) * OSTAGE;

#pragma unroll
        for (int ks = 0; ks < 2; ks++) {
            int kk = ks * 16 + fk;
            uint32_t fa[4][4], fb[2][4];
#pragma unroll
            for (int mi = 0; mi < 4; mi++)
                ldm4(fa[mi], stb + O_A +
                     (uint32_t)((mwarp + mi * 16 + frow) * (OLDK * 2) + kk * 2));
#pragma unroll
            for (int nb = 0; nb < 2; nb++)
                ldm4(fb[nb], stb + O_B +
                     (uint32_t)((nwarp + nb * 16 + frow) * (OLDK * 2) + kk * 2));
#pragma unroll
            for (int mi = 0; mi < 4; mi++)
#pragma unroll
                for (int nf = 0; nf < 4; nf++) {
                    int nb = nf >> 1, hi = nf & 1;
                    mma_f16(acc[mi][nf], fa[mi], fb[nb][hi], fb[nb][hi + 2]);
                }
        }
    }

    float cs0[4], cs1[4];
#pragma unroll
    for (int nf = 0; nf < 4; nf++) { cs0[nf] = 0.f; cs1[nf] = 0.f; }
#pragma unroll
    for (int mi = 0; mi < 4; mi++) {
        int row = mwarp + mi * 16 + (lane >> 2);
        float bi0 = bias[row], bi1 = bias[row + 8];
#pragma unroll
        for (int nf = 0; nf < 4; nf++) {
            acc[mi][nf][0] += bi0;
            acc[mi][nf][1] += bi0;
            acc[mi][nf][2] += bi1;
            acc[mi][nf][3] += bi1;
            cs0[nf] += acc[mi][nf][0] * acc[mi][nf][0] + acc[mi][nf][2] * acc[mi][nf][2];
            cs1[nf] += acc[mi][nf][1] * acc[mi][nf][1] + acc[mi][nf][3] * acc[mi][nf][3];
        }
    }
#pragma unroll
    for (int nf = 0; nf < 4; nf++) {
#pragma unroll
        for (int o = 4; o < 32; o <<= 1) {
            cs0[nf] += __shfl_xor_sync(0xFFFFFFFFu, cs0[nf], o);
            cs1[nf] += __shfl_xor_sync(0xFFFFFFFFu, cs1[nf], o);
        }
    }
    if (lane < 4) {
#pragma unroll
        for (int nf = 0; nf < 4; nf++) {
            int col = nwarp + nf * 8 + lane * 2;
            atomicAdd(&colsq[col], cs0[nf]);
            atomicAdd(&colsq[col + 1], cs1[nf]);
        }
    }
    __syncthreads();
    if (tid < 64) invs[tid] = 16.0f / fmaxf(sqrtf(colsq[tid]), 1e-12f);
    __syncthreads();

    float* ob = out + (size_t)b * CIN * HW + pos0;
#pragma unroll
    for (int mi = 0; mi < 4; mi++) {
        int row = mwarp + mi * 16 + (lane >> 2);
        float gr0 = gout[row], gr1 = gout[row + 8];
#pragma unroll
        for (int nf = 0; nf < 4; nf++) {
            int col = nwarp + nf * 8 + (lane & 3) * 2;
            float i0 = invs[col], i1 = invs[col + 1];
            *(float2*)(ob + (size_t)row * HW + col) =
                make_float2(acc[mi][nf][0] * i0 * gr0, acc[mi][nf][1] * i1 * gr0);
            *(float2*)(ob + (size_t)(row + 8) * HW + col) =
                make_float2(acc[mi][nf][2] * i0 * gr1, acc[mi][nf][3] * i1 * gr1);
        }
    }
}

// ---------------------------------------------------------------------------
extern "C" void kernel_launch(void* const* d_in, const int* in_sizes, int n_in,
                              void* d_out, int out_size) {
    const float* x      = (const float*)d_in[0];
    const float* g_in   = (const float*)d_in[1];
    const float* w_qkv  = (const float*)d_in[2];
    const float* mem_kv = (const float*)d_in[3];
    const float* w_out  = (const float*)d_in[4];
    const float* b_out  = (const float*)d_in[5];
    const float* g_out  = (const float*)d_in[6];
    float* out = (float*)d_out;

    float *rmax_ptr, *rinv_ptr, *part_ptr, *ctx_ptr;
    __half *w1_ptr, *wo1_ptr, *x1_ptr, *qkv_ptr, *ek_ptr, *a1_ptr;
    cudaGetSymbolAddress((void**)&w1_ptr,   g_w1);
    cudaGetSymbolAddress((void**)&wo1_ptr,  g_wo1);
    cudaGetSymbolAddress((void**)&x1_ptr,   g_x1);
    cudaGetSymbolAddress((void**)&qkv_ptr,  g_qkv);
    cudaGetSymbolAddress((void**)&ek_ptr,   g_ek);
    cudaGetSymbolAddress((void**)&rmax_ptr, g_rmax);
    cudaGetSymbolAddress((void**)&rinv_ptr, g_rinv);
    cudaGetSymbolAddress((void**)&part_ptr, g_part);
    cudaGetSymbolAddress((void**)&ctx_ptr,  g_ctx);
    cudaGetSymbolAddress((void**)&a1_ptr,   g_a1);

    cudaFuncSetAttribute(qkv_mma_kernel,
                         cudaFuncAttributeMaxDynamicSharedMemorySize, QSMTOT);
    cudaFuncSetAttribute(ctxpart_kernel,
                         cudaFuncAttributeMaxDynamicSharedMemorySize, CSMTOT);
    cudaFuncSetAttribute(outnorm_mma_kernel,
                         cudaFuncAttributeMaxDynamicSharedMemorySize, OSMTOT);

    wconv_kernel<<<(O3 * CIN + 255) / 256, 256>>>(w_qkv, g_in, w1_ptr);
    woconv_kernel<<<(CIN * HID + 255) / 256, 256>>>(w_out, wo1_ptr);
    xnorm_kernel<<<dim3(HW / 32, BATCH), 256>>>(x, x1_ptr);
    qkv_mma_kernel<<<dim3(HW / 128, O3 / 128, BATCH), 256, QSMTOT>>>(
        w1_ptr, x1_ptr, qkv_ptr);
    kstats_kernel<<<dim3(HD, NH, BATCH), 256>>>(qkv_ptr, mem_kv, rmax_ptr, rinv_ptr, ek_ptr);
    ctxpart_kernel<<<dim3(NC, NH, BATCH), 256, CSMTOT>>>(ek_ptr, qkv_ptr, part_ptr);
    ctxreduce_kernel<<<dim3(NH, BATCH), 256>>>(part_ptr, mem_kv, rmax_ptr, rinv_ptr, ctx_ptr);
    attend_kernel<<<dim3(HW / 128, NH, BATCH), 256>>>(qkv_ptr, ctx_ptr, a1_ptr);
    outnorm_mma_kernel<<<dim3(HW / 64, BATCH), 256, OSMTOT>>>(
        wo1_ptr, a1_ptr, b_out, g_out, out);
}